// round 1
// baseline (speedup 1.0000x reference)
#include <cuda_runtime.h>
#include <math.h>
#include <float.h>

#define D_MODEL  1024
#define N_HEADS  16
#define HEAD_DIM 64
#define BATCH    2
#define SEQ      2048
#define M_TOT    (BATCH * SEQ)     // 4096
#define N_QKV    (3 * D_MODEL)     // 3072

// Scratch (allocation-free rule: __device__ globals)
__device__ float g_qkv[(size_t)M_TOT * N_QKV];   // [4096, 3072] : q|k|v each [.., H, Hd]
__device__ float g_att[(size_t)M_TOT * D_MODEL]; // [4096, 1024] attention output

// ---------------------------------------------------------------------------
// C[m,n] = sum_k A[m,k] * B[n,k] + bias[n]   (both row-major, K-major dot)
// 128x128x8 tile, 256 threads, 8x8 per-thread microtile (split 4+4).
// ---------------------------------------------------------------------------
__global__ void __launch_bounds__(256) sgemm_nt_bias(
    const float* __restrict__ A, const float* __restrict__ B,
    const float* __restrict__ bias, float* __restrict__ C,
    int M, int N, int K)
{
    __shared__ float As[8][128];
    __shared__ float Bs[8][128];

    const int t  = threadIdx.x;
    const int tx = t & 15;
    const int ty = t >> 4;
    const int m0 = blockIdx.y * 128;
    const int n0 = blockIdx.x * 128;

    const int lr = t >> 1;        // 0..127 : tile row loaded by this thread
    const int lk = (t & 1) * 4;   // 0 or 4 : k sub-offset

    const float* Ag = A + (size_t)(m0 + lr) * K + lk;
    const float* Bg = B + (size_t)(n0 + lr) * K + lk;

    float acc[8][8];
#pragma unroll
    for (int i = 0; i < 8; i++)
#pragma unroll
        for (int j = 0; j < 8; j++) acc[i][j] = 0.0f;

    for (int kb = 0; kb < K; kb += 8) {
        float4 av = *(const float4*)(Ag + kb);
        float4 bv = *(const float4*)(Bg + kb);
        As[lk + 0][lr] = av.x; As[lk + 1][lr] = av.y;
        As[lk + 2][lr] = av.z; As[lk + 3][lr] = av.w;
        Bs[lk + 0][lr] = bv.x; Bs[lk + 1][lr] = bv.y;
        Bs[lk + 2][lr] = bv.z; Bs[lk + 3][lr] = bv.w;
        __syncthreads();

#pragma unroll
        for (int kk = 0; kk < 8; kk++) {
            float4 a0 = *(const float4*)&As[kk][ty * 4];
            float4 a1 = *(const float4*)&As[kk][64 + ty * 4];
            float4 b0 = *(const float4*)&Bs[kk][tx * 4];
            float4 b1 = *(const float4*)&Bs[kk][64 + tx * 4];
            float a[8] = {a0.x, a0.y, a0.z, a0.w, a1.x, a1.y, a1.z, a1.w};
            float b[8] = {b0.x, b0.y, b0.z, b0.w, b1.x, b1.y, b1.z, b1.w};
#pragma unroll
            for (int i = 0; i < 8; i++)
#pragma unroll
                for (int j = 0; j < 8; j++) acc[i][j] += a[i] * b[j];
        }
        __syncthreads();
    }

    float4 bi0 = *(const float4*)(bias + n0 + tx * 4);
    float4 bi1 = *(const float4*)(bias + n0 + 64 + tx * 4);
    const float bb[8] = {bi0.x, bi0.y, bi0.z, bi0.w, bi1.x, bi1.y, bi1.z, bi1.w};

#pragma unroll
    for (int i = 0; i < 8; i++) {
        int row = m0 + ((i < 4) ? (ty * 4 + i) : (64 + ty * 4 + i - 4));
        float4 c0 = make_float4(acc[i][0] + bb[0], acc[i][1] + bb[1],
                                acc[i][2] + bb[2], acc[i][3] + bb[3]);
        float4 c1 = make_float4(acc[i][4] + bb[4], acc[i][5] + bb[5],
                                acc[i][6] + bb[6], acc[i][7] + bb[7]);
        *(float4*)(C + (size_t)row * N + n0 + tx * 4)      = c0;
        *(float4*)(C + (size_t)row * N + n0 + 64 + tx * 4) = c1;
    }
}

// ---------------------------------------------------------------------------
// Fused causal flash attention, fp32.
// Grid: (S/64, H, B). Block: 256 threads (16x16), each owns a 4x4 microtile
// of the 64x64 score tile and a 4x4 microtile of the 64-wide O accumulator.
// ---------------------------------------------------------------------------
#define ATT_LDS 68  // padded row stride (floats) for the 64-wide smem tiles
#define ATT_SMEM_BYTES (4 * 64 * ATT_LDS * 4)

__global__ void __launch_bounds__(256) flash_attn(
    const float* __restrict__ qkv, float* __restrict__ att)
{
    extern __shared__ float sm[];
    float* Qt = sm;                     // [64 d][68] Qt[d][r] = Q[r][d]
    float* Kt = sm + 64 * ATT_LDS;      // [64 d][68] Kt[d][c] = K[c][d]
    float* Vs = sm + 2 * 64 * ATT_LDS;  // [64 k][68] Vs[k][d]
    float* Ps = sm + 3 * 64 * ATT_LDS;  // [64 r][68] Ps[r][k]

    const int t  = threadIdx.x;
    const int tx = t & 15;
    const int ty = t >> 4;
    const int qt = blockIdx.x;
    const int h  = blockIdx.y;
    const int b  = blockIdx.z;
    const int q0 = qt * 64;

    const float* qbase = qkv + (size_t)b * SEQ * N_QKV + h * HEAD_DIM;
    const float* kbase = qbase + D_MODEL;
    const float* vbase = qbase + 2 * D_MODEL;

    // Load Q tile transposed: Qt[d][r]
#pragma unroll
    for (int i = 0; i < 4; i++) {
        int idx = t + i * 256;          // 0..1023 over [64 r][16 d4]
        int r  = idx >> 4;
        int d4 = (idx & 15) * 4;
        float4 v = *(const float4*)(qbase + (size_t)(q0 + r) * N_QKV + d4);
        Qt[(d4 + 0) * ATT_LDS + r] = v.x;
        Qt[(d4 + 1) * ATT_LDS + r] = v.y;
        Qt[(d4 + 2) * ATT_LDS + r] = v.z;
        Qt[(d4 + 3) * ATT_LDS + r] = v.w;
    }

    float Mr[4], Lr[4], o[4][4];
#pragma unroll
    for (int i = 0; i < 4; i++) {
        Mr[i] = -FLT_MAX;
        Lr[i] = 0.0f;
#pragma unroll
        for (int j = 0; j < 4; j++) o[i][j] = 0.0f;
    }

    for (int kt = 0; kt <= qt; kt++) {
        const int k0 = kt * 64;
        // Load K transposed + V natural
#pragma unroll
        for (int i = 0; i < 4; i++) {
            int idx = t + i * 256;
            int r  = idx >> 4;
            int d4 = (idx & 15) * 4;
            float4 kv = *(const float4*)(kbase + (size_t)(k0 + r) * N_QKV + d4);
            Kt[(d4 + 0) * ATT_LDS + r] = kv.x;
            Kt[(d4 + 1) * ATT_LDS + r] = kv.y;
            Kt[(d4 + 2) * ATT_LDS + r] = kv.z;
            Kt[(d4 + 3) * ATT_LDS + r] = kv.w;
            float4 vv = *(const float4*)(vbase + (size_t)(k0 + r) * N_QKV + d4);
            *(float4*)&Vs[r * ATT_LDS + d4] = vv;
        }
        __syncthreads();

        // S = Q K^T for this thread's 4x4 microtile
        float s[4][4];
#pragma unroll
        for (int i = 0; i < 4; i++)
#pragma unroll
            for (int j = 0; j < 4; j++) s[i][j] = 0.0f;

#pragma unroll 8
        for (int d = 0; d < 64; d++) {
            float4 qa = *(const float4*)&Qt[d * ATT_LDS + ty * 4];
            float4 kb = *(const float4*)&Kt[d * ATT_LDS + tx * 4];
            float qa_[4] = {qa.x, qa.y, qa.z, qa.w};
            float kb_[4] = {kb.x, kb.y, kb.z, kb.w};
#pragma unroll
            for (int i = 0; i < 4; i++)
#pragma unroll
                for (int j = 0; j < 4; j++) s[i][j] += qa_[i] * kb_[j];
        }

        const float scale = 0.125f;  // 1/sqrt(64)
        const bool diag = (kt == qt);
#pragma unroll
        for (int i = 0; i < 4; i++) {
#pragma unroll
            for (int j = 0; j < 4; j++) {
                float v = s[i][j] * scale;
                if (diag && (k0 + tx * 4 + j > q0 + ty * 4 + i)) v = -FLT_MAX;
                s[i][j] = v;
            }
        }

        // Online softmax: row reductions over tx (16-lane xor butterflies)
        float f[4], p[4][4];
#pragma unroll
        for (int i = 0; i < 4; i++) {
            float tm = fmaxf(fmaxf(s[i][0], s[i][1]), fmaxf(s[i][2], s[i][3]));
#pragma unroll
            for (int off = 1; off < 16; off <<= 1)
                tm = fmaxf(tm, __shfl_xor_sync(0xffffffffu, tm, off));
            float Mn = fmaxf(Mr[i], tm);
            f[i] = __expf(Mr[i] - Mn);
            float rs = 0.0f;
#pragma unroll
            for (int j = 0; j < 4; j++) {
                p[i][j] = __expf(s[i][j] - Mn);
                rs += p[i][j];
            }
#pragma unroll
            for (int off = 1; off < 16; off <<= 1)
                rs += __shfl_xor_sync(0xffffffffu, rs, off);
            Lr[i] = Lr[i] * f[i] + rs;
            Mr[i] = Mn;
        }

        // Stage P to smem (row-major), rescale O
#pragma unroll
        for (int i = 0; i < 4; i++) {
            *(float4*)&Ps[(ty * 4 + i) * ATT_LDS + tx * 4] =
                make_float4(p[i][0], p[i][1], p[i][2], p[i][3]);
#pragma unroll
            for (int j = 0; j < 4; j++) o[i][j] *= f[i];
        }
        __syncthreads();

        // O += P V
#pragma unroll 8
        for (int k = 0; k < 64; k++) {
            float4 vv = *(const float4*)&Vs[k * ATT_LDS + tx * 4];
            float vv_[4] = {vv.x, vv.y, vv.z, vv.w};
            float pr[4];
#pragma unroll
            for (int i = 0; i < 4; i++) pr[i] = Ps[(ty * 4 + i) * ATT_LDS + k];
#pragma unroll
            for (int i = 0; i < 4; i++)
#pragma unroll
                for (int j = 0; j < 4; j++) o[i][j] += pr[i] * vv_[j];
        }
        __syncthreads();
    }

    // Normalize + write: att[b, q, h, d]  (col = h*64 + d)
#pragma unroll
    for (int i = 0; i < 4; i++) {
        float inv = 1.0f / Lr[i];
        float4 ov = make_float4(o[i][0] * inv, o[i][1] * inv,
                                o[i][2] * inv, o[i][3] * inv);
        size_t row = (size_t)b * SEQ + q0 + ty * 4 + i;
        *(float4*)(att + row * D_MODEL + h * HEAD_DIM + tx * 4) = ov;
    }
}

// ---------------------------------------------------------------------------
extern "C" void kernel_launch(void* const* d_in, const int* in_sizes, int n_in,
                              void* d_out, int out_size)
{
    const float* x     = (const float*)d_in[0];
    const float* qkv_w = (const float*)d_in[1];
    const float* qkv_b = (const float*)d_in[2];
    const float* out_w = (const float*)d_in[3];
    const float* out_b = (const float*)d_in[4];
    float* out = (float*)d_out;

    float *qkvbuf, *attbuf;
    cudaGetSymbolAddress((void**)&qkvbuf, g_qkv);
    cudaGetSymbolAddress((void**)&attbuf, g_att);
    cudaFuncSetAttribute(flash_attn, cudaFuncAttributeMaxDynamicSharedMemorySize,
                         ATT_SMEM_BYTES);

    // 1) QKV projection: [4096,3072] = x[4096,1024] @ qkv_w^T + b
    sgemm_nt_bias<<<dim3(N_QKV / 128, M_TOT / 128), 256>>>(
        x, qkv_w, qkv_b, qkvbuf, M_TOT, N_QKV, D_MODEL);

    // 2) Fused causal attention
    flash_attn<<<dim3(SEQ / 64, N_HEADS, BATCH), 256, ATT_SMEM_BYTES>>>(
        qkvbuf, attbuf);

    // 3) Output projection: [4096,1024] = att @ out_w^T + b
    sgemm_nt_bias<<<dim3(D_MODEL / 128, M_TOT / 128), 256>>>(
        attbuf, out_w, out_b, out, M_TOT, D_MODEL, D_MODEL);
}

// round 3
// speedup vs baseline: 1.5285x; 1.5285x over previous
#include <cuda_runtime.h>
#include <cuda_bf16.h>
#include <math.h>
#include <float.h>
#include <cstdint>

#define D_MODEL  1024
#define N_HEADS  16
#define HEAD_DIM 64
#define BATCH    2
#define SEQ      2048
#define M_TOT    (BATCH * SEQ)     // 4096
#define N_QKV    (3 * D_MODEL)     // 3072

// ---------------- scratch (allocation-free rule: __device__ globals) --------
__device__ float g_qkv[(size_t)M_TOT * N_QKV];   // fp32 QKV for attention
__device__ float g_att[(size_t)M_TOT * D_MODEL]; // fp32 attention output
__device__ __nv_bfloat16 g_xh[(size_t)M_TOT * D_MODEL];
__device__ __nv_bfloat16 g_xl[(size_t)M_TOT * D_MODEL];
__device__ __nv_bfloat16 g_wqh[(size_t)N_QKV * D_MODEL];
__device__ __nv_bfloat16 g_wql[(size_t)N_QKV * D_MODEL];
__device__ __nv_bfloat16 g_woh[(size_t)D_MODEL * D_MODEL];
__device__ __nv_bfloat16 g_wol[(size_t)D_MODEL * D_MODEL];
__device__ __nv_bfloat16 g_ah[(size_t)M_TOT * D_MODEL];
__device__ __nv_bfloat16 g_al[(size_t)M_TOT * D_MODEL];

// ---------------- helpers ---------------------------------------------------
__device__ __forceinline__ uint32_t smem_u32(const void* p) {
    uint32_t a;
    asm("{ .reg .u64 t; cvta.to.shared.u64 t, %1; cvt.u32.u64 %0, t; }"
        : "=r"(a) : "l"(p));
    return a;
}
__device__ __forceinline__ void cp_async16(uint32_t dst, const void* src) {
    asm volatile("cp.async.cg.shared.global [%0], [%1], 16;" :: "r"(dst), "l"(src)
                 : "memory");
}
__device__ __forceinline__ void ldsm_x4(uint32_t* r, uint32_t addr) {
    asm volatile("ldmatrix.sync.aligned.m8n8.x4.shared.b16 {%0,%1,%2,%3}, [%4];"
        : "=r"(r[0]), "=r"(r[1]), "=r"(r[2]), "=r"(r[3]) : "r"(addr));
}
__device__ __forceinline__ void mma16816(float* c, const uint32_t* a, const uint32_t* b) {
    asm volatile("mma.sync.aligned.m16n8k16.row.col.f32.bf16.bf16.f32 "
        "{%0,%1,%2,%3}, {%4,%5,%6,%7}, {%8,%9}, {%0,%1,%2,%3};"
        : "+f"(c[0]), "+f"(c[1]), "+f"(c[2]), "+f"(c[3])
        : "r"(a[0]), "r"(a[1]), "r"(a[2]), "r"(a[3]), "r"(b[0]), "r"(b[1]));
}

// ---------------- fp32 -> (bf16 hi, bf16 lo) split --------------------------
__global__ void __launch_bounds__(256) split_bf16(
    const float2* __restrict__ in, __nv_bfloat162* __restrict__ hi,
    __nv_bfloat162* __restrict__ lo, int n2)
{
    int i = blockIdx.x * blockDim.x + threadIdx.x;
    if (i < n2) {
        float2 v = in[i];
        __nv_bfloat16 hx = __float2bfloat16(v.x);
        __nv_bfloat16 hy = __float2bfloat16(v.y);
        float lx = v.x - __bfloat162float(hx);
        float ly = v.y - __bfloat162float(hy);
        hi[i] = __halves2bfloat162(hx, hy);
        lo[i] = __halves2bfloat162(__float2bfloat16(lx), __float2bfloat16(ly));
    }
}

// ---------------- mma.sync split-bf16 GEMM ----------------------------------
// C[m,n] = sum_k A[m,k]*B[n,k] + bias[n].  A,B K-major as (hi,lo) bf16.
// Block: 128x128 tile, 256 thr (8 warps, 4x2), BK=32, double-buffered cp.async.
#define BK 32
#define ASTR 40                         // padded smem stride (bf16 elems), 80 B
#define TILE_B (128 * ASTR * 2)         // 10240 B per operand tile
#define STAGE_B (4 * TILE_B)            // Ah, Al, Bh, Bl
#define GEMM_SMEM (2 * STAGE_B)         // 81920 B

__global__ void __launch_bounds__(256) gemm_mma_split(
    const __nv_bfloat16* __restrict__ Ah, const __nv_bfloat16* __restrict__ Al,
    const __nv_bfloat16* __restrict__ Bh, const __nv_bfloat16* __restrict__ Bl,
    const float* __restrict__ bias, float* __restrict__ C, int N, int K)
{
    extern __shared__ char smem[];
    const uint32_t sbase = smem_u32(smem);
    const int t = threadIdx.x, lane = t & 31, wid = t >> 5;
    const int wm0 = (wid & 3) * 32, wn0 = (wid >> 2) * 64;
    const int m0 = blockIdx.y * 128, n0 = blockIdx.x * 128;

    const __nv_bfloat16* srcs[4] = {Ah, Al, Bh, Bl};

    auto load = [&](int c, int s) {
        uint32_t stg = sbase + s * STAGE_B;
#pragma unroll
        for (int tile = 0; tile < 4; tile++) {
            int row0 = (tile < 2) ? m0 : n0;
            const __nv_bfloat16* src = srcs[tile];
#pragma unroll
            for (int it = 0; it < 2; it++) {
                int idx = t + it * 256;        // 0..511 over [128 r][4 seg]
                int r = idx >> 2, seg = idx & 3;
                cp_async16(stg + tile * TILE_B + r * (ASTR * 2) + seg * 16,
                           src + (size_t)(row0 + r) * K + c * BK + seg * 8);
            }
        }
        asm volatile("cp.async.commit_group;" ::: "memory");
    };

    float acc[16][4];
#pragma unroll
    for (int i = 0; i < 16; i++)
#pragma unroll
        for (int j = 0; j < 4; j++) acc[i][j] = 0.0f;

    const int NC = K / BK;
    load(0, 0);

    // precomputed intra-stage ldmatrix offsets
    const uint32_t a_off = (wm0 + (lane & 15)) * (ASTR * 2) + ((lane >> 4) << 3) * 2;
    const uint32_t b_off = (wn0 + ((lane >> 4) << 3) + (lane & 7)) * (ASTR * 2) +
                           (((lane >> 3) & 1) << 3) * 2;

    for (int c = 0; c < NC; c++) {
        const int s = c & 1;
        if (c + 1 < NC) {
            load(c + 1, 1 - s);
            asm volatile("cp.async.wait_group 1;" ::: "memory");
        } else {
            asm volatile("cp.async.wait_group 0;" ::: "memory");
        }
        __syncthreads();

        const uint32_t stg = sbase + s * STAGE_B;
#pragma unroll
        for (int kk = 0; kk < 2; kk++) {
            const uint32_t k0b = kk * 16 * 2;   // byte offset of k16 step
            uint32_t aHf[2][4], aLf[2][4], bHf[4][4], bLf[4][4];
#pragma unroll
            for (int mt = 0; mt < 2; mt++) {
                uint32_t off = a_off + mt * 16 * (ASTR * 2) + k0b;
                ldsm_x4(aHf[mt], stg + 0 * TILE_B + off);
                ldsm_x4(aLf[mt], stg + 1 * TILE_B + off);
            }
#pragma unroll
            for (int nt2 = 0; nt2 < 4; nt2++) {
                uint32_t off = b_off + nt2 * 16 * (ASTR * 2) + k0b;
                ldsm_x4(bHf[nt2], stg + 2 * TILE_B + off);
                ldsm_x4(bLf[nt2], stg + 3 * TILE_B + off);
            }
#pragma unroll
            for (int mt = 0; mt < 2; mt++)
#pragma unroll
                for (int nt = 0; nt < 8; nt++) {
                    float* c4 = acc[mt * 8 + nt];
                    const uint32_t* bh = &bHf[nt >> 1][(nt & 1) * 2];
                    const uint32_t* bl = &bLf[nt >> 1][(nt & 1) * 2];
                    mma16816(c4, aHf[mt], bh);
                    mma16816(c4, aHf[mt], bl);
                    mma16816(c4, aLf[mt], bh);
                }
        }
        __syncthreads();
    }

    // Epilogue: c0,c1 -> (row, col..col+1); c2,c3 -> (row+8, same cols)
    const int r0 = m0 + wm0 + (lane >> 2);
    const int c0l = (lane & 3) * 2;
#pragma unroll
    for (int mt = 0; mt < 2; mt++)
#pragma unroll
        for (int nt = 0; nt < 8; nt++) {
            const float* c4 = acc[mt * 8 + nt];
            int row = r0 + mt * 16;
            int col = n0 + wn0 + nt * 8 + c0l;
            float2 bi = *(const float2*)(bias + col);
            float2 v0 = make_float2(c4[0] + bi.x, c4[1] + bi.y);
            float2 v1 = make_float2(c4[2] + bi.x, c4[3] + bi.y);
            *(float2*)(C + (size_t)row * N + col) = v0;
            *(float2*)(C + (size_t)(row + 8) * N + col) = v1;
        }
}

// ---------------------------------------------------------------------------
// Fused causal flash attention, fp32 (unchanged, known-good).
// ---------------------------------------------------------------------------
#define ATT_LDS 68
#define ATT_SMEM_BYTES (4 * 64 * ATT_LDS * 4)

__global__ void __launch_bounds__(256) flash_attn(
    const float* __restrict__ qkv, float* __restrict__ att)
{
    extern __shared__ float sm[];
    float* Qt = sm;
    float* Kt = sm + 64 * ATT_LDS;
    float* Vs = sm + 2 * 64 * ATT_LDS;
    float* Ps = sm + 3 * 64 * ATT_LDS;

    const int t  = threadIdx.x;
    const int tx = t & 15;
    const int ty = t >> 4;
    const int qt = blockIdx.x;
    const int h  = blockIdx.y;
    const int b  = blockIdx.z;
    const int q0 = qt * 64;

    const float* qbase = qkv + (size_t)b * SEQ * N_QKV + h * HEAD_DIM;
    const float* kbase = qbase + D_MODEL;
    const float* vbase = qbase + 2 * D_MODEL;

#pragma unroll
    for (int i = 0; i < 4; i++) {
        int idx = t + i * 256;
        int r  = idx >> 4;
        int d4 = (idx & 15) * 4;
        float4 v = *(const float4*)(qbase + (size_t)(q0 + r) * N_QKV + d4);
        Qt[(d4 + 0) * ATT_LDS + r] = v.x;
        Qt[(d4 + 1) * ATT_LDS + r] = v.y;
        Qt[(d4 + 2) * ATT_LDS + r] = v.z;
        Qt[(d4 + 3) * ATT_LDS + r] = v.w;
    }

    float Mr[4], Lr[4], o[4][4];
#pragma unroll
    for (int i = 0; i < 4; i++) {
        Mr[i] = -FLT_MAX;
        Lr[i] = 0.0f;
#pragma unroll
        for (int j = 0; j < 4; j++) o[i][j] = 0.0f;
    }

    for (int kt = 0; kt <= qt; kt++) {
        const int k0 = kt * 64;
#pragma unroll
        for (int i = 0; i < 4; i++) {
            int idx = t + i * 256;
            int r  = idx >> 4;
            int d4 = (idx & 15) * 4;
            float4 kv = *(const float4*)(kbase + (size_t)(k0 + r) * N_QKV + d4);
            Kt[(d4 + 0) * ATT_LDS + r] = kv.x;
            Kt[(d4 + 1) * ATT_LDS + r] = kv.y;
            Kt[(d4 + 2) * ATT_LDS + r] = kv.z;
            Kt[(d4 + 3) * ATT_LDS + r] = kv.w;
            float4 vv = *(const float4*)(vbase + (size_t)(k0 + r) * N_QKV + d4);
            *(float4*)&Vs[r * ATT_LDS + d4] = vv;
        }
        __syncthreads();

        float s[4][4];
#pragma unroll
        for (int i = 0; i < 4; i++)
#pragma unroll
            for (int j = 0; j < 4; j++) s[i][j] = 0.0f;

#pragma unroll 8
        for (int d = 0; d < 64; d++) {
            float4 qa = *(const float4*)&Qt[d * ATT_LDS + ty * 4];
            float4 kb = *(const float4*)&Kt[d * ATT_LDS + tx * 4];
            float qa_[4] = {qa.x, qa.y, qa.z, qa.w};
            float kb_[4] = {kb.x, kb.y, kb.z, kb.w};
#pragma unroll
            for (int i = 0; i < 4; i++)
#pragma unroll
                for (int j = 0; j < 4; j++) s[i][j] += qa_[i] * kb_[j];
        }

        const float scale = 0.125f;
        const bool diag = (kt == qt);
#pragma unroll
        for (int i = 0; i < 4; i++) {
#pragma unroll
            for (int j = 0; j < 4; j++) {
                float v = s[i][j] * scale;
                if (diag && (k0 + tx * 4 + j > q0 + ty * 4 + i)) v = -FLT_MAX;
                s[i][j] = v;
            }
        }

        float f[4], p[4][4];
#pragma unroll
        for (int i = 0; i < 4; i++) {
            float tm = fmaxf(fmaxf(s[i][0], s[i][1]), fmaxf(s[i][2], s[i][3]));
#pragma unroll
            for (int off = 1; off < 16; off <<= 1)
                tm = fmaxf(tm, __shfl_xor_sync(0xffffffffu, tm, off));
            float Mn = fmaxf(Mr[i], tm);
            f[i] = __expf(Mr[i] - Mn);
            float rs = 0.0f;
#pragma unroll
            for (int j = 0; j < 4; j++) {
                p[i][j] = __expf(s[i][j] - Mn);
                rs += p[i][j];
            }
#pragma unroll
            for (int off = 1; off < 16; off <<= 1)
                rs += __shfl_xor_sync(0xffffffffu, rs, off);
            Lr[i] = Lr[i] * f[i] + rs;
            Mr[i] = Mn;
        }

#pragma unroll
        for (int i = 0; i < 4; i++) {
            *(float4*)&Ps[(ty * 4 + i) * ATT_LDS + tx * 4] =
                make_float4(p[i][0], p[i][1], p[i][2], p[i][3]);
#pragma unroll
            for (int j = 0; j < 4; j++) o[i][j] *= f[i];
        }
        __syncthreads();

#pragma unroll 8
        for (int k = 0; k < 64; k++) {
            float4 vv = *(const float4*)&Vs[k * ATT_LDS + tx * 4];
            float vv_[4] = {vv.x, vv.y, vv.z, vv.w};
            float pr[4];
#pragma unroll
            for (int i = 0; i < 4; i++) pr[i] = Ps[(ty * 4 + i) * ATT_LDS + k];
#pragma unroll
            for (int i = 0; i < 4; i++)
#pragma unroll
                for (int j = 0; j < 4; j++) o[i][j] += pr[i] * vv_[j];
        }
        __syncthreads();
    }

#pragma unroll
    for (int i = 0; i < 4; i++) {
        float inv = 1.0f / Lr[i];
        float4 ov = make_float4(o[i][0] * inv, o[i][1] * inv,
                                o[i][2] * inv, o[i][3] * inv);
        size_t row = (size_t)b * SEQ + q0 + ty * 4 + i;
        *(float4*)(att + row * D_MODEL + h * HEAD_DIM + tx * 4) = ov;
    }
}

// ---------------------------------------------------------------------------
extern "C" void kernel_launch(void* const* d_in, const int* in_sizes, int n_in,
                              void* d_out, int out_size)
{
    const float* x     = (const float*)d_in[0];
    const float* qkv_w = (const float*)d_in[1];
    const float* qkv_b = (const float*)d_in[2];
    const float* out_w = (const float*)d_in[3];
    const float* out_b = (const float*)d_in[4];
    float* out = (float*)d_out;

    float *qkvbuf, *attbuf;
    __nv_bfloat16 *xh, *xl, *wqh, *wql, *woh, *wol, *ah, *al;
    cudaGetSymbolAddress((void**)&qkvbuf, g_qkv);
    cudaGetSymbolAddress((void**)&attbuf, g_att);
    cudaGetSymbolAddress((void**)&xh, g_xh);
    cudaGetSymbolAddress((void**)&xl, g_xl);
    cudaGetSymbolAddress((void**)&wqh, g_wqh);
    cudaGetSymbolAddress((void**)&wql, g_wql);
    cudaGetSymbolAddress((void**)&woh, g_woh);
    cudaGetSymbolAddress((void**)&wol, g_wol);
    cudaGetSymbolAddress((void**)&ah, g_ah);
    cudaGetSymbolAddress((void**)&al, g_al);

    cudaFuncSetAttribute(flash_attn, cudaFuncAttributeMaxDynamicSharedMemorySize,
                         ATT_SMEM_BYTES);
    cudaFuncSetAttribute(gemm_mma_split, cudaFuncAttributeMaxDynamicSharedMemorySize,
                         GEMM_SMEM);

    int n2x = M_TOT * D_MODEL / 2;
    int n2q = N_QKV * D_MODEL / 2;
    int n2o = D_MODEL * D_MODEL / 2;
    split_bf16<<<(n2x + 255) / 256, 256>>>((const float2*)x,
        (__nv_bfloat162*)xh, (__nv_bfloat162*)xl, n2x);
    split_bf16<<<(n2q + 255) / 256, 256>>>((const float2*)qkv_w,
        (__nv_bfloat162*)wqh, (__nv_bfloat162*)wql, n2q);
    split_bf16<<<(n2o + 255) / 256, 256>>>((const float2*)out_w,
        (__nv_bfloat162*)woh, (__nv_bfloat162*)wol, n2o);

    // 1) QKV projection on tensor cores (mma.sync, split bf16)
    gemm_mma_split<<<dim3(N_QKV / 128, M_TOT / 128), 256, GEMM_SMEM>>>(
        xh, xl, wqh, wql, qkv_b, qkvbuf, N_QKV, D_MODEL);

    // 2) Fused causal attention (fp32)
    flash_attn<<<dim3(SEQ / 64, N_HEADS, BATCH), 256, ATT_SMEM_BYTES>>>(
        qkvbuf, attbuf);

    // 3) Split attention output, then output projection
    split_bf16<<<(n2x + 255) / 256, 256>>>((const float2*)attbuf,
        (__nv_bfloat162*)ah, (__nv_bfloat162*)al, n2x);
    gemm_mma_split<<<dim3(D_MODEL / 128, M_TOT / 128), 256, GEMM_SMEM>>>(
        ah, al, woh, wol, out_b, out, D_MODEL, D_MODEL);
}

// round 4
// speedup vs baseline: 2.8146x; 1.8414x over previous
#include <cuda_runtime.h>
#include <cuda_bf16.h>
#include <math.h>
#include <float.h>
#include <cstdint>

#define D_MODEL  1024
#define N_HEADS  16
#define HEAD_DIM 64
#define BATCH    2
#define SEQ      2048
#define M_TOT    (BATCH * SEQ)     // 4096
#define N_QKV    (3 * D_MODEL)     // 3072

// ---------------- scratch (allocation-free rule: __device__ globals) --------
__device__ __nv_bfloat16 g_qkvh[(size_t)M_TOT * N_QKV];
__device__ __nv_bfloat16 g_qkvl[(size_t)M_TOT * N_QKV];
__device__ __nv_bfloat16 g_xh[(size_t)M_TOT * D_MODEL];
__device__ __nv_bfloat16 g_xl[(size_t)M_TOT * D_MODEL];
__device__ __nv_bfloat16 g_wqh[(size_t)N_QKV * D_MODEL];
__device__ __nv_bfloat16 g_wql[(size_t)N_QKV * D_MODEL];
__device__ __nv_bfloat16 g_woh[(size_t)D_MODEL * D_MODEL];
__device__ __nv_bfloat16 g_wol[(size_t)D_MODEL * D_MODEL];
__device__ __nv_bfloat16 g_ah[(size_t)M_TOT * D_MODEL];
__device__ __nv_bfloat16 g_al[(size_t)M_TOT * D_MODEL];

// ---------------- helpers ---------------------------------------------------
__device__ __forceinline__ uint32_t smem_u32(const void* p) {
    uint32_t a;
    asm("{ .reg .u64 t; cvta.to.shared.u64 t, %1; cvt.u32.u64 %0, t; }"
        : "=r"(a) : "l"(p));
    return a;
}
__device__ __forceinline__ void cp_async16(uint32_t dst, const void* src) {
    asm volatile("cp.async.cg.shared.global [%0], [%1], 16;" :: "r"(dst), "l"(src)
                 : "memory");
}
__device__ __forceinline__ void ldsm_x4(uint32_t* r, uint32_t addr) {
    asm volatile("ldmatrix.sync.aligned.m8n8.x4.shared.b16 {%0,%1,%2,%3}, [%4];"
        : "=r"(r[0]), "=r"(r[1]), "=r"(r[2]), "=r"(r[3]) : "r"(addr));
}
__device__ __forceinline__ void ldsm_x4_t(uint32_t* r, uint32_t addr) {
    asm volatile("ldmatrix.sync.aligned.m8n8.x4.trans.shared.b16 {%0,%1,%2,%3}, [%4];"
        : "=r"(r[0]), "=r"(r[1]), "=r"(r[2]), "=r"(r[3]) : "r"(addr));
}
__device__ __forceinline__ void mma16816(float* c, const uint32_t* a, const uint32_t* b) {
    asm volatile("mma.sync.aligned.m16n8k16.row.col.f32.bf16.bf16.f32 "
        "{%0,%1,%2,%3}, {%4,%5,%6,%7}, {%8,%9}, {%0,%1,%2,%3};"
        : "+f"(c[0]), "+f"(c[1]), "+f"(c[2]), "+f"(c[3])
        : "r"(a[0]), "r"(a[1]), "r"(a[2]), "r"(a[3]), "r"(b[0]), "r"(b[1]));
}
__device__ __forceinline__ void split2(float a, float b, uint32_t& hi, uint32_t& lo) {
    __nv_bfloat16 ha = __float2bfloat16(a), hb = __float2bfloat16(b);
    __nv_bfloat162 hv = __halves2bfloat162(ha, hb);
    __nv_bfloat162 lv = __halves2bfloat162(
        __float2bfloat16(a - __bfloat162float(ha)),
        __float2bfloat16(b - __bfloat162float(hb)));
    hi = *(uint32_t*)&hv; lo = *(uint32_t*)&lv;
}

// ---------------- fp32 -> (bf16 hi, bf16 lo) split --------------------------
__global__ void __launch_bounds__(256) split_bf16(
    const float2* __restrict__ in, __nv_bfloat162* __restrict__ hi,
    __nv_bfloat162* __restrict__ lo, int n2)
{
    int i = blockIdx.x * blockDim.x + threadIdx.x;
    if (i < n2) {
        float2 v = in[i];
        __nv_bfloat16 hx = __float2bfloat16(v.x);
        __nv_bfloat16 hy = __float2bfloat16(v.y);
        hi[i] = __halves2bfloat162(hx, hy);
        lo[i] = __halves2bfloat162(__float2bfloat16(v.x - __bfloat162float(hx)),
                                   __float2bfloat16(v.y - __bfloat162float(hy)));
    }
}

// ---------------- mma.sync split-bf16 GEMM ----------------------------------
// C[m,n] = sum_k A[m,k]*B[n,k] + bias[n].  A,B K-major (hi,lo) bf16.
// If split_out: writes (Ch,Cl) bf16; else writes fp32 C.
#define BK 32
#define ASTR 40
#define TILE_B (128 * ASTR * 2)
#define STAGE_B (4 * TILE_B)
#define GEMM_SMEM (2 * STAGE_B)

__global__ void __launch_bounds__(256) gemm_mma_split(
    const __nv_bfloat16* __restrict__ Ah, const __nv_bfloat16* __restrict__ Al,
    const __nv_bfloat16* __restrict__ Bh, const __nv_bfloat16* __restrict__ Bl,
    const float* __restrict__ bias, float* __restrict__ C,
    __nv_bfloat16* __restrict__ Ch, __nv_bfloat16* __restrict__ Cl,
    int N, int K, int split_out)
{
    extern __shared__ char smem[];
    const uint32_t sbase = smem_u32(smem);
    const int t = threadIdx.x, lane = t & 31, wid = t >> 5;
    const int wm0 = (wid & 3) * 32, wn0 = (wid >> 2) * 64;
    const int m0 = blockIdx.y * 128, n0 = blockIdx.x * 128;

    const __nv_bfloat16* srcs[4] = {Ah, Al, Bh, Bl};

    auto load = [&](int c, int s) {
        uint32_t stg = sbase + s * STAGE_B;
#pragma unroll
        for (int tile = 0; tile < 4; tile++) {
            int row0 = (tile < 2) ? m0 : n0;
            const __nv_bfloat16* src = srcs[tile];
#pragma unroll
            for (int it = 0; it < 2; it++) {
                int idx = t + it * 256;
                int r = idx >> 2, seg = idx & 3;
                cp_async16(stg + tile * TILE_B + r * (ASTR * 2) + seg * 16,
                           src + (size_t)(row0 + r) * K + c * BK + seg * 8);
            }
        }
        asm volatile("cp.async.commit_group;" ::: "memory");
    };

    float acc[16][4];
#pragma unroll
    for (int i = 0; i < 16; i++)
#pragma unroll
        for (int j = 0; j < 4; j++) acc[i][j] = 0.0f;

    const int NC = K / BK;
    load(0, 0);

    const uint32_t a_off = (wm0 + (lane & 15)) * (ASTR * 2) + ((lane >> 4) << 3) * 2;
    const uint32_t b_off = (wn0 + ((lane >> 4) << 3) + (lane & 7)) * (ASTR * 2) +
                           (((lane >> 3) & 1) << 3) * 2;

    for (int c = 0; c < NC; c++) {
        const int s = c & 1;
        if (c + 1 < NC) {
            load(c + 1, 1 - s);
            asm volatile("cp.async.wait_group 1;" ::: "memory");
        } else {
            asm volatile("cp.async.wait_group 0;" ::: "memory");
        }
        __syncthreads();

        const uint32_t stg = sbase + s * STAGE_B;
#pragma unroll
        for (int kk = 0; kk < 2; kk++) {
            const uint32_t k0b = kk * 16 * 2;
            uint32_t aHf[2][4], aLf[2][4], bHf[4][4], bLf[4][4];
#pragma unroll
            for (int mt = 0; mt < 2; mt++) {
                uint32_t off = a_off + mt * 16 * (ASTR * 2) + k0b;
                ldsm_x4(aHf[mt], stg + 0 * TILE_B + off);
                ldsm_x4(aLf[mt], stg + 1 * TILE_B + off);
            }
#pragma unroll
            for (int nt2 = 0; nt2 < 4; nt2++) {
                uint32_t off = b_off + nt2 * 16 * (ASTR * 2) + k0b;
                ldsm_x4(bHf[nt2], stg + 2 * TILE_B + off);
                ldsm_x4(bLf[nt2], stg + 3 * TILE_B + off);
            }
#pragma unroll
            for (int mt = 0; mt < 2; mt++)
#pragma unroll
                for (int nt = 0; nt < 8; nt++) {
                    float* c4 = acc[mt * 8 + nt];
                    const uint32_t* bh = &bHf[nt >> 1][(nt & 1) * 2];
                    const uint32_t* bl = &bLf[nt >> 1][(nt & 1) * 2];
                    mma16816(c4, aHf[mt], bh);
                    mma16816(c4, aHf[mt], bl);
                    mma16816(c4, aLf[mt], bh);
                }
        }
        __syncthreads();
    }

    const int r0 = m0 + wm0 + (lane >> 2);
    const int c0l = (lane & 3) * 2;
#pragma unroll
    for (int mt = 0; mt < 2; mt++)
#pragma unroll
        for (int nt = 0; nt < 8; nt++) {
            const float* c4 = acc[mt * 8 + nt];
            int row = r0 + mt * 16;
            int col = n0 + wn0 + nt * 8 + c0l;
            float2 bi = *(const float2*)(bias + col);
            float v0 = c4[0] + bi.x, v1 = c4[1] + bi.y;
            float v2 = c4[2] + bi.x, v3 = c4[3] + bi.y;
            if (split_out) {
                uint32_t h0, l0, h1, l1;
                split2(v0, v1, h0, l0);
                split2(v2, v3, h1, l1);
                *(uint32_t*)(Ch + (size_t)row * N + col) = h0;
                *(uint32_t*)(Cl + (size_t)row * N + col) = l0;
                *(uint32_t*)(Ch + (size_t)(row + 8) * N + col) = h1;
                *(uint32_t*)(Cl + (size_t)(row + 8) * N + col) = l1;
            } else {
                *(float2*)(C + (size_t)row * N + col) = make_float2(v0, v1);
                *(float2*)(C + (size_t)(row + 8) * N + col) = make_float2(v2, v3);
            }
        }
}

// ---------------------------------------------------------------------------
// Tensor-core causal flash attention (split bf16, 3-term).
// Block: 128 Q rows, 8 warps (16 rows each); KV tiles of 64, double-buffered.
// ---------------------------------------------------------------------------
#define AT_STR 72                          // smem stride in bf16 (144 B)
#define Q_TILE_B (128 * AT_STR * 2)        // 18432
#define KV_TILE_B (64 * AT_STR * 2)        // 9216
#define KV_STAGE_B (4 * KV_TILE_B)         // Kh,Kl,Vh,Vl
#define ATT_SMEM (2 * Q_TILE_B + 2 * KV_STAGE_B)  // 110592

__global__ void __launch_bounds__(256, 1) flash_attn_mma(
    const __nv_bfloat16* __restrict__ qkvh, const __nv_bfloat16* __restrict__ qkvl,
    __nv_bfloat16* __restrict__ ah, __nv_bfloat16* __restrict__ al)
{
    extern __shared__ char smem[];
    const uint32_t sb = smem_u32(smem);
    const uint32_t QH = 0, QL = Q_TILE_B, ST0 = 2 * Q_TILE_B;
    const int t = threadIdx.x, l = t & 31, w = t >> 5;
    const int qt = (int)(gridDim.x - 1 - blockIdx.x);   // heavy tiles first
    const int h = blockIdx.y, b = blockIdx.z;
    const int q0 = qt * 128;
    const size_t tok0 = (size_t)b * SEQ;

    // Q tile load (hi, lo)
#pragma unroll
    for (int it = 0; it < 4; it++) {
        int idx = t + it * 256;             // 0..1023 over [128 r][8 seg]
        int r = idx >> 3, seg = idx & 7;
        size_t src = (tok0 + q0 + r) * N_QKV + h * HEAD_DIM + seg * 8;
        uint32_t dst = (r * AT_STR + seg * 8) * 2;
        cp_async16(sb + QH + dst, qkvh + src);
        cp_async16(sb + QL + dst, qkvl + src);
    }
    asm volatile("cp.async.commit_group;" ::: "memory");

    auto load_kv = [&](int kt, int s) {
        uint32_t stg = sb + ST0 + s * KV_STAGE_B;
        int k0 = kt * 64;
#pragma unroll
        for (int it = 0; it < 2; it++) {
            int idx = t + it * 256;         // 0..511 over [64 r][8 seg]
            int r = idx >> 3, seg = idx & 7;
            size_t srcK = (tok0 + k0 + r) * N_QKV + D_MODEL + h * HEAD_DIM + seg * 8;
            uint32_t dst = (r * AT_STR + seg * 8) * 2;
            cp_async16(stg + 0 * KV_TILE_B + dst, qkvh + srcK);
            cp_async16(stg + 1 * KV_TILE_B + dst, qkvl + srcK);
            cp_async16(stg + 2 * KV_TILE_B + dst, qkvh + srcK + D_MODEL);
            cp_async16(stg + 3 * KV_TILE_B + dst, qkvl + srcK + D_MODEL);
        }
        asm volatile("cp.async.commit_group;" ::: "memory");
    };

    load_kv(0, 0);
    asm volatile("cp.async.wait_group 1;" ::: "memory");  // Q ready
    __syncthreads();

    // Hoist Q fragments (4 k-steps, hi+lo)
    uint32_t qfh[4][4], qfl[4][4];
    const uint32_t a_off = ((w * 16 + (l & 15)) * AT_STR + (l >> 4) * 8) * 2;
#pragma unroll
    for (int ks = 0; ks < 4; ks++) {
        ldsm_x4(qfh[ks], sb + QH + a_off + ks * 32);
        ldsm_x4(qfl[ks], sb + QL + a_off + ks * 32);
    }

    float M0 = -1e30f, M1 = -1e30f, L0 = 0.f, L1 = 0.f;
    float o[8][4];
#pragma unroll
    for (int i = 0; i < 8; i++)
#pragma unroll
        for (int j = 0; j < 4; j++) o[i][j] = 0.f;

    const uint32_t kb_off = (((l & 7) + ((l >> 4) << 3)) * AT_STR +
                             ((l >> 3) & 1) * 8) * 2;
    const uint32_t vb_off = ((l & 15) * AT_STR + (l >> 4) * 8) * 2;
    const int row0 = q0 + w * 16 + (l >> 2);
    const int colq = (l & 3) * 2;
    const int NT = 2 * qt + 2;

    for (int kt = 0; kt < NT; kt++) {
        if (kt + 1 < NT) {
            load_kv(kt + 1, (kt + 1) & 1);
            asm volatile("cp.async.wait_group 1;" ::: "memory");
        } else {
            asm volatile("cp.async.wait_group 0;" ::: "memory");
        }
        __syncthreads();
        const uint32_t stg = sb + ST0 + (kt & 1) * KV_STAGE_B;

        // S = Q K^T (3-term split)
        float sacc[8][4];
#pragma unroll
        for (int i = 0; i < 8; i++)
#pragma unroll
            for (int j = 0; j < 4; j++) sacc[i][j] = 0.f;

#pragma unroll
        for (int ks = 0; ks < 4; ks++) {
#pragma unroll
            for (int np = 0; np < 4; np++) {
                uint32_t bh[4], bl[4];
                uint32_t o2 = (np * 16 * AT_STR + ks * 16) * 2;
                ldsm_x4(bh, stg + 0 * KV_TILE_B + kb_off + o2);
                ldsm_x4(bl, stg + 1 * KV_TILE_B + kb_off + o2);
                mma16816(sacc[2 * np], qfh[ks], bh);
                mma16816(sacc[2 * np], qfh[ks], bl);
                mma16816(sacc[2 * np], qfl[ks], bh);
                mma16816(sacc[2 * np + 1], qfh[ks], bh + 2);
                mma16816(sacc[2 * np + 1], qfh[ks], bl + 2);
                mma16816(sacc[2 * np + 1], qfl[ks], bh + 2);
            }
        }

        // scale + causal mask
        const int k0 = kt * 64;
        const bool dm = (kt >= 2 * qt);
#pragma unroll
        for (int nt = 0; nt < 8; nt++) {
            int colb = k0 + nt * 8 + colq;
#pragma unroll
            for (int j = 0; j < 4; j++) {
                float v = sacc[nt][j] * 0.125f;
                if (dm && (colb + (j & 1)) > (row0 + (j >> 1) * 8)) v = -1e30f;
                sacc[nt][j] = v;
            }
        }

        // online softmax (rows row0, row0+8); quad reduce over lanes xor 1,2
        float m0 = -1e30f, m1 = -1e30f;
#pragma unroll
        for (int nt = 0; nt < 8; nt++) {
            m0 = fmaxf(m0, fmaxf(sacc[nt][0], sacc[nt][1]));
            m1 = fmaxf(m1, fmaxf(sacc[nt][2], sacc[nt][3]));
        }
        m0 = fmaxf(m0, __shfl_xor_sync(~0u, m0, 1));
        m0 = fmaxf(m0, __shfl_xor_sync(~0u, m0, 2));
        m1 = fmaxf(m1, __shfl_xor_sync(~0u, m1, 1));
        m1 = fmaxf(m1, __shfl_xor_sync(~0u, m1, 2));
        float Mn0 = fmaxf(M0, m0), Mn1 = fmaxf(M1, m1);
        float f0 = __expf(M0 - Mn0), f1 = __expf(M1 - Mn1);
        float rs0 = 0.f, rs1 = 0.f;
#pragma unroll
        for (int nt = 0; nt < 8; nt++) {
            sacc[nt][0] = __expf(sacc[nt][0] - Mn0);
            sacc[nt][1] = __expf(sacc[nt][1] - Mn0);
            sacc[nt][2] = __expf(sacc[nt][2] - Mn1);
            sacc[nt][3] = __expf(sacc[nt][3] - Mn1);
            rs0 += sacc[nt][0] + sacc[nt][1];
            rs1 += sacc[nt][2] + sacc[nt][3];
        }
        rs0 += __shfl_xor_sync(~0u, rs0, 1);
        rs0 += __shfl_xor_sync(~0u, rs0, 2);
        rs1 += __shfl_xor_sync(~0u, rs1, 1);
        rs1 += __shfl_xor_sync(~0u, rs1, 2);
        L0 = L0 * f0 + rs0; L1 = L1 * f1 + rs1;
        M0 = Mn0; M1 = Mn1;

#pragma unroll
        for (int nt = 0; nt < 8; nt++) {
            o[nt][0] *= f0; o[nt][1] *= f0;
            o[nt][2] *= f1; o[nt][3] *= f1;
        }

        // O += P V (P converted to A-frags in registers, split 3-term)
#pragma unroll
        for (int ks = 0; ks < 4; ks++) {
            uint32_t ph[4], pl[4];
            split2(sacc[2 * ks][0], sacc[2 * ks][1], ph[0], pl[0]);
            split2(sacc[2 * ks][2], sacc[2 * ks][3], ph[1], pl[1]);
            split2(sacc[2 * ks + 1][0], sacc[2 * ks + 1][1], ph[2], pl[2]);
            split2(sacc[2 * ks + 1][2], sacc[2 * ks + 1][3], ph[3], pl[3]);
#pragma unroll
            for (int np = 0; np < 4; np++) {
                uint32_t vh[4], vl[4];
                uint32_t o2 = (ks * 16 * AT_STR + np * 16) * 2;
                ldsm_x4_t(vh, stg + 2 * KV_TILE_B + vb_off + o2);
                ldsm_x4_t(vl, stg + 3 * KV_TILE_B + vb_off + o2);
                mma16816(o[2 * np], ph, vh);
                mma16816(o[2 * np], ph, vl);
                mma16816(o[2 * np], pl, vh);
                mma16816(o[2 * np + 1], ph, vh + 2);
                mma16816(o[2 * np + 1], ph, vl + 2);
                mma16816(o[2 * np + 1], pl, vh + 2);
            }
        }
        __syncthreads();
    }

    // normalize + write split bf16 att output: [token][h*64 + col]
    const float i0 = 1.f / L0, i1 = 1.f / L1;
#pragma unroll
    for (int nt = 0; nt < 8; nt++) {
        int col = h * HEAD_DIM + nt * 8 + colq;
        uint32_t h0, l0r, h1, l1r;
        split2(o[nt][0] * i0, o[nt][1] * i0, h0, l0r);
        split2(o[nt][2] * i1, o[nt][3] * i1, h1, l1r);
        size_t r0 = (tok0 + row0) * D_MODEL + col;
        size_t r1 = (tok0 + row0 + 8) * D_MODEL + col;
        *(uint32_t*)(ah + r0) = h0;
        *(uint32_t*)(al + r0) = l0r;
        *(uint32_t*)(ah + r1) = h1;
        *(uint32_t*)(al + r1) = l1r;
    }
}

// ---------------------------------------------------------------------------
extern "C" void kernel_launch(void* const* d_in, const int* in_sizes, int n_in,
                              void* d_out, int out_size)
{
    const float* x     = (const float*)d_in[0];
    const float* qkv_w = (const float*)d_in[1];
    const float* qkv_b = (const float*)d_in[2];
    const float* out_w = (const float*)d_in[3];
    const float* out_b = (const float*)d_in[4];
    float* out = (float*)d_out;

    __nv_bfloat16 *qkvh, *qkvl, *xh, *xl, *wqh, *wql, *woh, *wol, *ah, *al;
    cudaGetSymbolAddress((void**)&qkvh, g_qkvh);
    cudaGetSymbolAddress((void**)&qkvl, g_qkvl);
    cudaGetSymbolAddress((void**)&xh, g_xh);
    cudaGetSymbolAddress((void**)&xl, g_xl);
    cudaGetSymbolAddress((void**)&wqh, g_wqh);
    cudaGetSymbolAddress((void**)&wql, g_wql);
    cudaGetSymbolAddress((void**)&woh, g_woh);
    cudaGetSymbolAddress((void**)&wol, g_wol);
    cudaGetSymbolAddress((void**)&ah, g_ah);
    cudaGetSymbolAddress((void**)&al, g_al);

    cudaFuncSetAttribute(gemm_mma_split, cudaFuncAttributeMaxDynamicSharedMemorySize,
                         GEMM_SMEM);
    cudaFuncSetAttribute(flash_attn_mma, cudaFuncAttributeMaxDynamicSharedMemorySize,
                         ATT_SMEM);

    int n2x = M_TOT * D_MODEL / 2;
    int n2q = N_QKV * D_MODEL / 2;
    int n2o = D_MODEL * D_MODEL / 2;
    split_bf16<<<(n2x + 255) / 256, 256>>>((const float2*)x,
        (__nv_bfloat162*)xh, (__nv_bfloat162*)xl, n2x);
    split_bf16<<<(n2q + 255) / 256, 256>>>((const float2*)qkv_w,
        (__nv_bfloat162*)wqh, (__nv_bfloat162*)wql, n2q);
    split_bf16<<<(n2o + 255) / 256, 256>>>((const float2*)out_w,
        (__nv_bfloat162*)woh, (__nv_bfloat162*)wol, n2o);

    // 1) QKV projection -> split bf16 output directly
    gemm_mma_split<<<dim3(N_QKV / 128, M_TOT / 128), 256, GEMM_SMEM>>>(
        xh, xl, wqh, wql, qkv_b, nullptr, qkvh, qkvl, N_QKV, D_MODEL, 1);

    // 2) Tensor-core causal flash attention -> split bf16 output
    flash_attn_mma<<<dim3(SEQ / 128, N_HEADS, BATCH), 256, ATT_SMEM>>>(
        qkvh, qkvl, ah, al);

    // 3) Output projection -> fp32 final
    gemm_mma_split<<<dim3(D_MODEL / 128, M_TOT / 128), 256, GEMM_SMEM>>>(
        ah, al, woh, wol, out_b, out, nullptr, nullptr, D_MODEL, D_MODEL, 0);
}

// round 5
// speedup vs baseline: 3.0386x; 1.0796x over previous
#include <cuda_runtime.h>
#include <cuda_bf16.h>
#include <math.h>
#include <float.h>
#include <cstdint>

#define D_MODEL  1024
#define N_HEADS  16
#define HEAD_DIM 64
#define BATCH    2
#define SEQ      2048
#define M_TOT    (BATCH * SEQ)     // 4096
#define N_QKV    (3 * D_MODEL)     // 3072

// ---------------- scratch (allocation-free rule: __device__ globals) --------
__device__ __nv_bfloat16 g_qkvh[(size_t)M_TOT * N_QKV];
__device__ __nv_bfloat16 g_qkvl[(size_t)M_TOT * N_QKV];
__device__ __nv_bfloat16 g_xh[(size_t)M_TOT * D_MODEL];
__device__ __nv_bfloat16 g_xl[(size_t)M_TOT * D_MODEL];
__device__ __nv_bfloat16 g_wqh[(size_t)N_QKV * D_MODEL];
__device__ __nv_bfloat16 g_wql[(size_t)N_QKV * D_MODEL];
__device__ __nv_bfloat16 g_woh[(size_t)D_MODEL * D_MODEL];
__device__ __nv_bfloat16 g_wol[(size_t)D_MODEL * D_MODEL];
__device__ __nv_bfloat16 g_ah[(size_t)M_TOT * D_MODEL];
__device__ __nv_bfloat16 g_al[(size_t)M_TOT * D_MODEL];

// ---------------- helpers ---------------------------------------------------
__device__ __forceinline__ uint32_t smem_u32(const void* p) {
    uint32_t a;
    asm("{ .reg .u64 t; cvta.to.shared.u64 t, %1; cvt.u32.u64 %0, t; }"
        : "=r"(a) : "l"(p));
    return a;
}
__device__ __forceinline__ void cp_async16(uint32_t dst, const void* src) {
    asm volatile("cp.async.cg.shared.global [%0], [%1], 16;" :: "r"(dst), "l"(src)
                 : "memory");
}
__device__ __forceinline__ void ldsm_x4(uint32_t* r, uint32_t addr) {
    asm volatile("ldmatrix.sync.aligned.m8n8.x4.shared.b16 {%0,%1,%2,%3}, [%4];"
        : "=r"(r[0]), "=r"(r[1]), "=r"(r[2]), "=r"(r[3]) : "r"(addr));
}
__device__ __forceinline__ void ldsm_x4_t(uint32_t* r, uint32_t addr) {
    asm volatile("ldmatrix.sync.aligned.m8n8.x4.trans.shared.b16 {%0,%1,%2,%3}, [%4];"
        : "=r"(r[0]), "=r"(r[1]), "=r"(r[2]), "=r"(r[3]) : "r"(addr));
}
__device__ __forceinline__ void mma16816(float* c, const uint32_t* a, const uint32_t* b) {
    asm volatile("mma.sync.aligned.m16n8k16.row.col.f32.bf16.bf16.f32 "
        "{%0,%1,%2,%3}, {%4,%5,%6,%7}, {%8,%9}, {%0,%1,%2,%3};"
        : "+f"(c[0]), "+f"(c[1]), "+f"(c[2]), "+f"(c[3])
        : "r"(a[0]), "r"(a[1]), "r"(a[2]), "r"(a[3]), "r"(b[0]), "r"(b[1]));
}
__device__ __forceinline__ void split2(float a, float b, uint32_t& hi, uint32_t& lo) {
    __nv_bfloat16 ha = __float2bfloat16(a), hb = __float2bfloat16(b);
    __nv_bfloat162 hv = __halves2bfloat162(ha, hb);
    __nv_bfloat162 lv = __halves2bfloat162(
        __float2bfloat16(a - __bfloat162float(ha)),
        __float2bfloat16(b - __bfloat162float(hb)));
    hi = *(uint32_t*)&hv; lo = *(uint32_t*)&lv;
}

// ---------------- fp32 -> (bf16 hi, bf16 lo) split --------------------------
__global__ void __launch_bounds__(256) split_bf16(
    const float2* __restrict__ in, __nv_bfloat162* __restrict__ hi,
    __nv_bfloat162* __restrict__ lo, int n2)
{
    int i = blockIdx.x * blockDim.x + threadIdx.x;
    if (i < n2) {
        float2 v = in[i];
        __nv_bfloat16 hx = __float2bfloat16(v.x);
        __nv_bfloat16 hy = __float2bfloat16(v.y);
        hi[i] = __halves2bfloat162(hx, hy);
        lo[i] = __halves2bfloat162(__float2bfloat16(v.x - __bfloat162float(hx)),
                                   __float2bfloat16(v.y - __bfloat162float(hy)));
    }
}

// ---------------- mma.sync split-bf16 GEMM, 3-stage pipeline ----------------
// C[m,n] = sum_k A[m,k]*B[n,k] + bias[n].  A,B K-major (hi,lo) bf16.
// 128x128 tile, BK=32 (64B rows), XOR-swizzled smem, 3-stage cp.async ring.
#define GTILE_B  (128 * 64)          // 8192 B per operand tile
#define GSTAGE_B (4 * GTILE_B)       // Ah, Al, Bh, Bl = 32768 B
#define GEMM_SMEM (3 * GSTAGE_B)     // 98304 B

__device__ __forceinline__ uint32_t gswz(uint32_t r, uint32_t s) {
    return r * 64 + (((s ^ ((r >> 1) & 3)) & 3) << 4);
}

__global__ void __launch_bounds__(256, 2) gemm_mma_split(
    const __nv_bfloat16* __restrict__ Ah, const __nv_bfloat16* __restrict__ Al,
    const __nv_bfloat16* __restrict__ Bh, const __nv_bfloat16* __restrict__ Bl,
    const float* __restrict__ bias, float* __restrict__ C,
    __nv_bfloat16* __restrict__ Ch, __nv_bfloat16* __restrict__ Cl,
    int N, int K, int split_out)
{
    extern __shared__ char smem[];
    const uint32_t sbase = smem_u32(smem);
    const int t = threadIdx.x, lane = t & 31, wid = t >> 5;
    const int wm0 = (wid & 3) * 32, wn0 = (wid >> 2) * 64;
    const int m0 = blockIdx.y * 128, n0 = blockIdx.x * 128;

    const __nv_bfloat16* srcs[4] = {Ah, Al, Bh, Bl};

    auto load = [&](int c, int st) {
        uint32_t stg = sbase + st * GSTAGE_B;
#pragma unroll
        for (int i = 0; i < 8; i++) {
            int idx = t + i * 256;            // 0..2047: [tile 4][row 128][seg 4]
            int tile = idx >> 9;
            int r = (idx >> 2) & 127;
            int s = idx & 3;
            int row0 = (tile < 2) ? m0 : n0;
            cp_async16(stg + tile * GTILE_B + gswz(r, s),
                       srcs[tile] + (size_t)(row0 + r) * K + c * 32 + s * 8);
        }
        asm volatile("cp.async.commit_group;" ::: "memory");
    };

    float acc[16][4];
#pragma unroll
    for (int i = 0; i < 16; i++)
#pragma unroll
        for (int j = 0; j < 4; j++) acc[i][j] = 0.0f;

    // per-lane fragment addressing (swizzle row-XOR is constant per lane)
    const int l15 = lane & 15;
    const uint32_t arx = (l15 >> 1) & 3;          // row>>1 & 3 for A rows
    uint32_t ar64[2];
    ar64[0] = (wm0 + l15) * 64;
    ar64[1] = (wm0 + 16 + l15) * 64;
    const uint32_t brbase = wn0 + ((lane >> 4) << 3) + (lane & 7);
    const uint32_t brx = (brbase >> 1) & 3;
    const uint32_t bsel = (lane >> 3) & 1;

    const int NC = K / 32;
    load(0, 0);
    load(1, 1);

    int st = 0;
    for (int c = 0; c < NC; c++) {
        if (c == NC - 1)
            asm volatile("cp.async.wait_group 0;" ::: "memory");
        else
            asm volatile("cp.async.wait_group 1;" ::: "memory");
        __syncthreads();
        if (c + 2 < NC) {
            int st2 = st + 2; if (st2 >= 3) st2 -= 3;
            load(c + 2, st2);
        }

        const uint32_t stg = sbase + st * GSTAGE_B;
#pragma unroll
        for (int kk = 0; kk < 2; kk++) {
            uint32_t aHf[2][4], aLf[2][4];
            const uint32_t sA = kk * 2 + (lane >> 4);
#pragma unroll
            for (int mt = 0; mt < 2; mt++) {
                uint32_t col = ((sA ^ arx) & 3) << 4;
                ldsm_x4(aHf[mt], stg + 0 * GTILE_B + ar64[mt] + col);
                ldsm_x4(aLf[mt], stg + 1 * GTILE_B + ar64[mt] + col);
            }
            const uint32_t sB = kk * 2 + bsel;
            const uint32_t bcol = ((sB ^ brx) & 3) << 4;
#pragma unroll
            for (int nt2 = 0; nt2 < 4; nt2++) {
                uint32_t bh[4], bl[4];
                uint32_t baddr = (brbase + nt2 * 16) * 64 + bcol;
                ldsm_x4(bh, stg + 2 * GTILE_B + baddr);
                ldsm_x4(bl, stg + 3 * GTILE_B + baddr);
#pragma unroll
                for (int mt = 0; mt < 2; mt++) {
                    float* c0 = acc[mt * 8 + nt2 * 2];
                    float* c1 = acc[mt * 8 + nt2 * 2 + 1];
                    mma16816(c0, aHf[mt], bh);
                    mma16816(c0, aHf[mt], bl);
                    mma16816(c0, aLf[mt], bh);
                    mma16816(c1, aHf[mt], bh + 2);
                    mma16816(c1, aHf[mt], bl + 2);
                    mma16816(c1, aLf[mt], bh + 2);
                }
            }
        }
        st++; if (st >= 3) st -= 3;
    }

    const int r0 = m0 + wm0 + (lane >> 2);
    const int c0l = (lane & 3) * 2;
#pragma unroll
    for (int mt = 0; mt < 2; mt++)
#pragma unroll
        for (int nt = 0; nt < 8; nt++) {
            const float* c4 = acc[mt * 8 + nt];
            int row = r0 + mt * 16;
            int col = n0 + wn0 + nt * 8 + c0l;
            float2 bi = *(const float2*)(bias + col);
            float v0 = c4[0] + bi.x, v1 = c4[1] + bi.y;
            float v2 = c4[2] + bi.x, v3 = c4[3] + bi.y;
            if (split_out) {
                uint32_t h0, l0, h1, l1;
                split2(v0, v1, h0, l0);
                split2(v2, v3, h1, l1);
                *(uint32_t*)(Ch + (size_t)row * N + col) = h0;
                *(uint32_t*)(Cl + (size_t)row * N + col) = l0;
                *(uint32_t*)(Ch + (size_t)(row + 8) * N + col) = h1;
                *(uint32_t*)(Cl + (size_t)(row + 8) * N + col) = l1;
            } else {
                *(float2*)(C + (size_t)row * N + col) = make_float2(v0, v1);
                *(float2*)(C + (size_t)(row + 8) * N + col) = make_float2(v2, v3);
            }
        }
}

// ---------------------------------------------------------------------------
// Tensor-core causal flash attention (split bf16, 3-term). Unchanged (passing).
// ---------------------------------------------------------------------------
#define AT_STR 72                          // smem stride in bf16 (144 B)
#define Q_TILE_B (128 * AT_STR * 2)        // 18432
#define KV_TILE_B (64 * AT_STR * 2)        // 9216
#define KV_STAGE_B (4 * KV_TILE_B)         // Kh,Kl,Vh,Vl
#define ATT_SMEM (2 * Q_TILE_B + 2 * KV_STAGE_B)  // 110592

__global__ void __launch_bounds__(256, 1) flash_attn_mma(
    const __nv_bfloat16* __restrict__ qkvh, const __nv_bfloat16* __restrict__ qkvl,
    __nv_bfloat16* __restrict__ ah, __nv_bfloat16* __restrict__ al)
{
    extern __shared__ char smem[];
    const uint32_t sb = smem_u32(smem);
    const uint32_t QH = 0, QL = Q_TILE_B, ST0 = 2 * Q_TILE_B;
    const int t = threadIdx.x, l = t & 31, w = t >> 5;
    const int qt = (int)(gridDim.x - 1 - blockIdx.x);   // heavy tiles first
    const int h = blockIdx.y, b = blockIdx.z;
    const int q0 = qt * 128;
    const size_t tok0 = (size_t)b * SEQ;

#pragma unroll
    for (int it = 0; it < 4; it++) {
        int idx = t + it * 256;
        int r = idx >> 3, seg = idx & 7;
        size_t src = (tok0 + q0 + r) * N_QKV + h * HEAD_DIM + seg * 8;
        uint32_t dst = (r * AT_STR + seg * 8) * 2;
        cp_async16(sb + QH + dst, qkvh + src);
        cp_async16(sb + QL + dst, qkvl + src);
    }
    asm volatile("cp.async.commit_group;" ::: "memory");

    auto load_kv = [&](int kt, int s) {
        uint32_t stg = sb + ST0 + s * KV_STAGE_B;
        int k0 = kt * 64;
#pragma unroll
        for (int it = 0; it < 2; it++) {
            int idx = t + it * 256;
            int r = idx >> 3, seg = idx & 7;
            size_t srcK = (tok0 + k0 + r) * N_QKV + D_MODEL + h * HEAD_DIM + seg * 8;
            uint32_t dst = (r * AT_STR + seg * 8) * 2;
            cp_async16(stg + 0 * KV_TILE_B + dst, qkvh + srcK);
            cp_async16(stg + 1 * KV_TILE_B + dst, qkvl + srcK);
            cp_async16(stg + 2 * KV_TILE_B + dst, qkvh + srcK + D_MODEL);
            cp_async16(stg + 3 * KV_TILE_B + dst, qkvl + srcK + D_MODEL);
        }
        asm volatile("cp.async.commit_group;" ::: "memory");
    };

    load_kv(0, 0);
    asm volatile("cp.async.wait_group 1;" ::: "memory");
    __syncthreads();

    uint32_t qfh[4][4], qfl[4][4];
    const uint32_t a_off = ((w * 16 + (l & 15)) * AT_STR + (l >> 4) * 8) * 2;
#pragma unroll
    for (int ks = 0; ks < 4; ks++) {
        ldsm_x4(qfh[ks], sb + QH + a_off + ks * 32);
        ldsm_x4(qfl[ks], sb + QL + a_off + ks * 32);
    }

    float M0 = -1e30f, M1 = -1e30f, L0 = 0.f, L1 = 0.f;
    float o[8][4];
#pragma unroll
    for (int i = 0; i < 8; i++)
#pragma unroll
        for (int j = 0; j < 4; j++) o[i][j] = 0.f;

    const uint32_t kb_off = (((l & 7) + ((l >> 4) << 3)) * AT_STR +
                             ((l >> 3) & 1) * 8) * 2;
    const uint32_t vb_off = ((l & 15) * AT_STR + (l >> 4) * 8) * 2;
    const int row0 = q0 + w * 16 + (l >> 2);
    const int colq = (l & 3) * 2;
    const int NT = 2 * qt + 2;

    for (int kt = 0; kt < NT; kt++) {
        if (kt + 1 < NT) {
            load_kv(kt + 1, (kt + 1) & 1);
            asm volatile("cp.async.wait_group 1;" ::: "memory");
        } else {
            asm volatile("cp.async.wait_group 0;" ::: "memory");
        }
        __syncthreads();
        const uint32_t stg = sb + ST0 + (kt & 1) * KV_STAGE_B;

        float sacc[8][4];
#pragma unroll
        for (int i = 0; i < 8; i++)
#pragma unroll
            for (int j = 0; j < 4; j++) sacc[i][j] = 0.f;

#pragma unroll
        for (int ks = 0; ks < 4; ks++) {
#pragma unroll
            for (int np = 0; np < 4; np++) {
                uint32_t bh[4], bl[4];
                uint32_t o2 = (np * 16 * AT_STR + ks * 16) * 2;
                ldsm_x4(bh, stg + 0 * KV_TILE_B + kb_off + o2);
                ldsm_x4(bl, stg + 1 * KV_TILE_B + kb_off + o2);
                mma16816(sacc[2 * np], qfh[ks], bh);
                mma16816(sacc[2 * np], qfh[ks], bl);
                mma16816(sacc[2 * np], qfl[ks], bh);
                mma16816(sacc[2 * np + 1], qfh[ks], bh + 2);
                mma16816(sacc[2 * np + 1], qfh[ks], bl + 2);
                mma16816(sacc[2 * np + 1], qfl[ks], bh + 2);
            }
        }

        const int k0 = kt * 64;
        const bool dm = (kt >= 2 * qt);
#pragma unroll
        for (int nt = 0; nt < 8; nt++) {
            int colb = k0 + nt * 8 + colq;
#pragma unroll
            for (int j = 0; j < 4; j++) {
                float v = sacc[nt][j] * 0.125f;
                if (dm && (colb + (j & 1)) > (row0 + (j >> 1) * 8)) v = -1e30f;
                sacc[nt][j] = v;
            }
        }

        float m0 = -1e30f, m1 = -1e30f;
#pragma unroll
        for (int nt = 0; nt < 8; nt++) {
            m0 = fmaxf(m0, fmaxf(sacc[nt][0], sacc[nt][1]));
            m1 = fmaxf(m1, fmaxf(sacc[nt][2], sacc[nt][3]));
        }
        m0 = fmaxf(m0, __shfl_xor_sync(~0u, m0, 1));
        m0 = fmaxf(m0, __shfl_xor_sync(~0u, m0, 2));
        m1 = fmaxf(m1, __shfl_xor_sync(~0u, m1, 1));
        m1 = fmaxf(m1, __shfl_xor_sync(~0u, m1, 2));
        float Mn0 = fmaxf(M0, m0), Mn1 = fmaxf(M1, m1);
        float f0 = __expf(M0 - Mn0), f1 = __expf(M1 - Mn1);
        float rs0 = 0.f, rs1 = 0.f;
#pragma unroll
        for (int nt = 0; nt < 8; nt++) {
            sacc[nt][0] = __expf(sacc[nt][0] - Mn0);
            sacc[nt][1] = __expf(sacc[nt][1] - Mn0);
            sacc[nt][2] = __expf(sacc[nt][2] - Mn1);
            sacc[nt][3] = __expf(sacc[nt][3] - Mn1);
            rs0 += sacc[nt][0] + sacc[nt][1];
            rs1 += sacc[nt][2] + sacc[nt][3];
        }
        rs0 += __shfl_xor_sync(~0u, rs0, 1);
        rs0 += __shfl_xor_sync(~0u, rs0, 2);
        rs1 += __shfl_xor_sync(~0u, rs1, 1);
        rs1 += __shfl_xor_sync(~0u, rs1, 2);
        L0 = L0 * f0 + rs0; L1 = L1 * f1 + rs1;
        M0 = Mn0; M1 = Mn1;

#pragma unroll
        for (int nt = 0; nt < 8; nt++) {
            o[nt][0] *= f0; o[nt][1] *= f0;
            o[nt][2] *= f1; o[nt][3] *= f1;
        }

#pragma unroll
        for (int ks = 0; ks < 4; ks++) {
            uint32_t ph[4], pl[4];
            split2(sacc[2 * ks][0], sacc[2 * ks][1], ph[0], pl[0]);
            split2(sacc[2 * ks][2], sacc[2 * ks][3], ph[1], pl[1]);
            split2(sacc[2 * ks + 1][0], sacc[2 * ks + 1][1], ph[2], pl[2]);
            split2(sacc[2 * ks + 1][2], sacc[2 * ks + 1][3], ph[3], pl[3]);
#pragma unroll
            for (int np = 0; np < 4; np++) {
                uint32_t vh[4], vl[4];
                uint32_t o2 = (ks * 16 * AT_STR + np * 16) * 2;
                ldsm_x4_t(vh, stg + 2 * KV_TILE_B + vb_off + o2);
                ldsm_x4_t(vl, stg + 3 * KV_TILE_B + vb_off + o2);
                mma16816(o[2 * np], ph, vh);
                mma16816(o[2 * np], ph, vl);
                mma16816(o[2 * np], pl, vh);
                mma16816(o[2 * np + 1], ph, vh + 2);
                mma16816(o[2 * np + 1], ph, vl + 2);
                mma16816(o[2 * np + 1], pl, vh + 2);
            }
        }
        __syncthreads();
    }

    const float i0 = 1.f / L0, i1 = 1.f / L1;
#pragma unroll
    for (int nt = 0; nt < 8; nt++) {
        int col = h * HEAD_DIM + nt * 8 + colq;
        uint32_t h0, l0r, h1, l1r;
        split2(o[nt][0] * i0, o[nt][1] * i0, h0, l0r);
        split2(o[nt][2] * i1, o[nt][3] * i1, h1, l1r);
        size_t r0 = (tok0 + row0) * D_MODEL + col;
        size_t r1 = (tok0 + row0 + 8) * D_MODEL + col;
        *(uint32_t*)(ah + r0) = h0;
        *(uint32_t*)(al + r0) = l0r;
        *(uint32_t*)(ah + r1) = h1;
        *(uint32_t*)(al + r1) = l1r;
    }
}

// ---------------------------------------------------------------------------
extern "C" void kernel_launch(void* const* d_in, const int* in_sizes, int n_in,
                              void* d_out, int out_size)
{
    const float* x     = (const float*)d_in[0];
    const float* qkv_w = (const float*)d_in[1];
    const float* qkv_b = (const float*)d_in[2];
    const float* out_w = (const float*)d_in[3];
    const float* out_b = (const float*)d_in[4];
    float* out = (float*)d_out;

    __nv_bfloat16 *qkvh, *qkvl, *xh, *xl, *wqh, *wql, *woh, *wol, *ah, *al;
    cudaGetSymbolAddress((void**)&qkvh, g_qkvh);
    cudaGetSymbolAddress((void**)&qkvl, g_qkvl);
    cudaGetSymbolAddress((void**)&xh, g_xh);
    cudaGetSymbolAddress((void**)&xl, g_xl);
    cudaGetSymbolAddress((void**)&wqh, g_wqh);
    cudaGetSymbolAddress((void**)&wql, g_wql);
    cudaGetSymbolAddress((void**)&woh, g_woh);
    cudaGetSymbolAddress((void**)&wol, g_wol);
    cudaGetSymbolAddress((void**)&ah, g_ah);
    cudaGetSymbolAddress((void**)&al, g_al);

    cudaFuncSetAttribute(gemm_mma_split, cudaFuncAttributeMaxDynamicSharedMemorySize,
                         GEMM_SMEM);
    cudaFuncSetAttribute(flash_attn_mma, cudaFuncAttributeMaxDynamicSharedMemorySize,
                         ATT_SMEM);

    int n2x = M_TOT * D_MODEL / 2;
    int n2q = N_QKV * D_MODEL / 2;
    int n2o = D_MODEL * D_MODEL / 2;
    split_bf16<<<(n2x + 255) / 256, 256>>>((const float2*)x,
        (__nv_bfloat162*)xh, (__nv_bfloat162*)xl, n2x);
    split_bf16<<<(n2q + 255) / 256, 256>>>((const float2*)qkv_w,
        (__nv_bfloat162*)wqh, (__nv_bfloat162*)wql, n2q);
    split_bf16<<<(n2o + 255) / 256, 256>>>((const float2*)out_w,
        (__nv_bfloat162*)woh, (__nv_bfloat162*)wol, n2o);

    // 1) QKV projection -> split bf16 output directly
    gemm_mma_split<<<dim3(N_QKV / 128, M_TOT / 128), 256, GEMM_SMEM>>>(
        xh, xl, wqh, wql, qkv_b, nullptr, qkvh, qkvl, N_QKV, D_MODEL, 1);

    // 2) Tensor-core causal flash attention -> split bf16 output
    flash_attn_mma<<<dim3(SEQ / 128, N_HEADS, BATCH), 256, ATT_SMEM>>>(
        qkvh, qkvl, ah, al);

    // 3) Output projection -> fp32 final
    gemm_mma_split<<<dim3(D_MODEL / 128, M_TOT / 128), 256, GEMM_SMEM>>>(
        ah, al, woh, wol, out_b, out, nullptr, nullptr, D_MODEL, D_MODEL, 0);
}

// round 6
// speedup vs baseline: 4.1569x; 1.3680x over previous
#include <cuda_runtime.h>
#include <cuda_fp16.h>
#include <math.h>
#include <float.h>
#include <cstdint>

#define D_MODEL  1024
#define N_HEADS  16
#define HEAD_DIM 64
#define BATCH    2
#define SEQ      2048
#define M_TOT    (BATCH * SEQ)     // 4096
#define N_QKV    (3 * D_MODEL)     // 3072

// ---------------- scratch (allocation-free rule: __device__ globals) --------
__device__ __half g_qkvh[(size_t)M_TOT * N_QKV];   // fp16(qkv)
__device__ __half g_qkvl[(size_t)M_TOT * N_QKV];   // residual (used for Q only)
__device__ __half g_xh[(size_t)M_TOT * D_MODEL];
__device__ __half g_xl[(size_t)M_TOT * D_MODEL];
__device__ __half g_wq[(size_t)N_QKV * D_MODEL];   // fp16 weights (B-side, single)
__device__ __half g_wo[(size_t)D_MODEL * D_MODEL];
__device__ __half g_ah[(size_t)M_TOT * D_MODEL];
__device__ __half g_al[(size_t)M_TOT * D_MODEL];

// ---------------- helpers ---------------------------------------------------
__device__ __forceinline__ uint32_t smem_u32(const void* p) {
    uint32_t a;
    asm("{ .reg .u64 t; cvta.to.shared.u64 t, %1; cvt.u32.u64 %0, t; }"
        : "=r"(a) : "l"(p));
    return a;
}
__device__ __forceinline__ void cp_async16(uint32_t dst, const void* src) {
    asm volatile("cp.async.cg.shared.global [%0], [%1], 16;" :: "r"(dst), "l"(src)
                 : "memory");
}
__device__ __forceinline__ void ldsm_x4(uint32_t* r, uint32_t addr) {
    asm volatile("ldmatrix.sync.aligned.m8n8.x4.shared.b16 {%0,%1,%2,%3}, [%4];"
        : "=r"(r[0]), "=r"(r[1]), "=r"(r[2]), "=r"(r[3]) : "r"(addr));
}
__device__ __forceinline__ void ldsm_x4_t(uint32_t* r, uint32_t addr) {
    asm volatile("ldmatrix.sync.aligned.m8n8.x4.trans.shared.b16 {%0,%1,%2,%3}, [%4];"
        : "=r"(r[0]), "=r"(r[1]), "=r"(r[2]), "=r"(r[3]) : "r"(addr));
}
__device__ __forceinline__ void mma16816(float* c, const uint32_t* a, const uint32_t* b) {
    asm volatile("mma.sync.aligned.m16n8k16.row.col.f32.f16.f16.f32 "
        "{%0,%1,%2,%3}, {%4,%5,%6,%7}, {%8,%9}, {%0,%1,%2,%3};"
        : "+f"(c[0]), "+f"(c[1]), "+f"(c[2]), "+f"(c[3])
        : "r"(a[0]), "r"(a[1]), "r"(a[2]), "r"(a[3]), "r"(b[0]), "r"(b[1]));
}
__device__ __forceinline__ void split2h(float a, float b, uint32_t& hi, uint32_t& lo) {
    __half2 h = __floats2half2_rn(a, b);
    float2 hf = __half22float2(h);
    __half2 l = __floats2half2_rn(a - hf.x, b - hf.y);
    hi = *(uint32_t*)&h; lo = *(uint32_t*)&l;
}

// ---------------- fp32 -> fp16 (hi, lo) split / round -----------------------
__global__ void __launch_bounds__(256) split_fp16(
    const float2* __restrict__ in, __half2* __restrict__ hi,
    __half2* __restrict__ lo, int n2)
{
    int i = blockIdx.x * blockDim.x + threadIdx.x;
    if (i < n2) {
        float2 v = in[i];
        __half2 h = __floats2half2_rn(v.x, v.y);
        float2 hf = __half22float2(h);
        hi[i] = h;
        lo[i] = __floats2half2_rn(v.x - hf.x, v.y - hf.y);
    }
}
__global__ void __launch_bounds__(256) round_fp16(
    const float2* __restrict__ in, __half2* __restrict__ out, int n2)
{
    int i = blockIdx.x * blockDim.x + threadIdx.x;
    if (i < n2) {
        float2 v = in[i];
        out[i] = __floats2half2_rn(v.x, v.y);
    }
}

// ---------------- mma.sync fp16 2-term GEMM, 4-stage pipeline ---------------
// C[m,n] = sum_k A[m,k]*B[n,k] + bias[n].  A K-major (hi,lo) fp16, B fp16.
#define GTILE_B  (128 * 64)          // 8192 B per operand tile (BK=32)
#define GSTAGE_B (3 * GTILE_B)       // Ah, Al, B = 24576 B
#define GEMM_SMEM (4 * GSTAGE_B)     // 98304 B

__device__ __forceinline__ uint32_t gswz(uint32_t r, uint32_t s) {
    return r * 64 + (((s ^ ((r >> 1) & 3)) & 3) << 4);
}

__global__ void __launch_bounds__(256, 2) gemm_mma_split(
    const __half* __restrict__ Ah, const __half* __restrict__ Al,
    const __half* __restrict__ Bh,
    const float* __restrict__ bias, float* __restrict__ C,
    __half* __restrict__ Ch, __half* __restrict__ Cl,
    int N, int K, int split_out)
{
    extern __shared__ char smem[];
    const uint32_t sbase = smem_u32(smem);
    const int t = threadIdx.x, lane = t & 31, wid = t >> 5;
    const int wm0 = (wid & 3) * 32, wn0 = (wid >> 2) * 64;
    const int m0 = blockIdx.y * 128, n0 = blockIdx.x * 128;

    const __half* srcs[3] = {Ah, Al, Bh};

    auto load = [&](int c, int st) {
        uint32_t stg = sbase + st * GSTAGE_B;
#pragma unroll
        for (int i = 0; i < 6; i++) {
            int idx = t + i * 256;            // 0..1535: [tile 3][row 128][seg 4]
            int tile = idx >> 9;
            int r = (idx >> 2) & 127;
            int s = idx & 3;
            int row0 = (tile < 2) ? m0 : n0;
            cp_async16(stg + tile * GTILE_B + gswz(r, s),
                       srcs[tile] + (size_t)(row0 + r) * K + c * 32 + s * 8);
        }
        asm volatile("cp.async.commit_group;" ::: "memory");
    };

    float acc[16][4];
#pragma unroll
    for (int i = 0; i < 16; i++)
#pragma unroll
        for (int j = 0; j < 4; j++) acc[i][j] = 0.0f;

    const int l15 = lane & 15;
    const uint32_t arx = (l15 >> 1) & 3;
    uint32_t ar64[2];
    ar64[0] = (wm0 + l15) * 64;
    ar64[1] = (wm0 + 16 + l15) * 64;
    const uint32_t brbase = wn0 + ((lane >> 4) << 3) + (lane & 7);
    const uint32_t brx = (brbase >> 1) & 3;
    const uint32_t bsel = (lane >> 3) & 1;

    const int NC = K / 32;
    load(0, 0); load(1, 1); load(2, 2);

    for (int c = 0; c < NC; c++) {
        if (c < NC - 2)
            asm volatile("cp.async.wait_group 2;" ::: "memory");
        else if (c == NC - 2)
            asm volatile("cp.async.wait_group 1;" ::: "memory");
        else
            asm volatile("cp.async.wait_group 0;" ::: "memory");
        __syncthreads();
        if (c + 3 < NC) load(c + 3, (c + 3) & 3);

        const uint32_t stg = sbase + (c & 3) * GSTAGE_B;
#pragma unroll
        for (int kk = 0; kk < 2; kk++) {
            uint32_t aHf[2][4], aLf[2][4];
            const uint32_t sA = kk * 2 + (lane >> 4);
#pragma unroll
            for (int mt = 0; mt < 2; mt++) {
                uint32_t col = ((sA ^ arx) & 3) << 4;
                ldsm_x4(aHf[mt], stg + 0 * GTILE_B + ar64[mt] + col);
                ldsm_x4(aLf[mt], stg + 1 * GTILE_B + ar64[mt] + col);
            }
            const uint32_t sB = kk * 2 + bsel;
            const uint32_t bcol = ((sB ^ brx) & 3) << 4;
#pragma unroll
            for (int nt2 = 0; nt2 < 4; nt2++) {
                uint32_t bh[4];
                uint32_t baddr = (brbase + nt2 * 16) * 64 + bcol;
                ldsm_x4(bh, stg + 2 * GTILE_B + baddr);
#pragma unroll
                for (int mt = 0; mt < 2; mt++) {
                    float* c0 = acc[mt * 8 + nt2 * 2];
                    float* c1 = acc[mt * 8 + nt2 * 2 + 1];
                    mma16816(c0, aHf[mt], bh);
                    mma16816(c0, aLf[mt], bh);
                    mma16816(c1, aHf[mt], bh + 2);
                    mma16816(c1, aLf[mt], bh + 2);
                }
            }
        }
    }

    const int r0 = m0 + wm0 + (lane >> 2);
    const int c0l = (lane & 3) * 2;
#pragma unroll
    for (int mt = 0; mt < 2; mt++)
#pragma unroll
        for (int nt = 0; nt < 8; nt++) {
            const float* c4 = acc[mt * 8 + nt];
            int row = r0 + mt * 16;
            int col = n0 + wn0 + nt * 8 + c0l;
            float2 bi = *(const float2*)(bias + col);
            float v0 = c4[0] + bi.x, v1 = c4[1] + bi.y;
            float v2 = c4[2] + bi.x, v3 = c4[3] + bi.y;
            if (split_out) {
                uint32_t h0, l0, h1, l1;
                split2h(v0, v1, h0, l0);
                split2h(v2, v3, h1, l1);
                *(uint32_t*)(Ch + (size_t)row * N + col) = h0;
                *(uint32_t*)(Cl + (size_t)row * N + col) = l0;
                *(uint32_t*)(Ch + (size_t)(row + 8) * N + col) = h1;
                *(uint32_t*)(Cl + (size_t)(row + 8) * N + col) = l1;
            } else {
                *(float2*)(C + (size_t)row * N + col) = make_float2(v0, v1);
                *(float2*)(C + (size_t)(row + 8) * N + col) = make_float2(v2, v3);
            }
        }
}

// ---------------------------------------------------------------------------
// Tensor-core causal flash attention, fp16 2-term (Q split; K,V single fp16).
// ---------------------------------------------------------------------------
#define AT_STR 72                          // smem stride in fp16 (144 B)
#define Q_TILE_B (128 * AT_STR * 2)        // 18432
#define KV_TILE_B (64 * AT_STR * 2)        // 9216
#define KV_STAGE_B (2 * KV_TILE_B)         // K, V
#define ATT_SMEM (2 * Q_TILE_B + 2 * KV_STAGE_B)  // 73728

__global__ void __launch_bounds__(256, 2) flash_attn_mma(
    const __half* __restrict__ qkvh, const __half* __restrict__ qkvl,
    __half* __restrict__ ah, __half* __restrict__ al)
{
    extern __shared__ char smem[];
    const uint32_t sb = smem_u32(smem);
    const uint32_t QH = 0, QL = Q_TILE_B, ST0 = 2 * Q_TILE_B;
    const int t = threadIdx.x, l = t & 31, w = t >> 5;
    const int qt = (int)(gridDim.x - 1 - blockIdx.x);   // heavy tiles first
    const int h = blockIdx.y, b = blockIdx.z;
    const int q0 = qt * 128;
    const size_t tok0 = (size_t)b * SEQ;

#pragma unroll
    for (int it = 0; it < 4; it++) {
        int idx = t + it * 256;
        int r = idx >> 3, seg = idx & 7;
        size_t src = (tok0 + q0 + r) * N_QKV + h * HEAD_DIM + seg * 8;
        uint32_t dst = (r * AT_STR + seg * 8) * 2;
        cp_async16(sb + QH + dst, qkvh + src);
        cp_async16(sb + QL + dst, qkvl + src);
    }
    asm volatile("cp.async.commit_group;" ::: "memory");

    auto load_kv = [&](int kt, int s) {
        uint32_t stg = sb + ST0 + s * KV_STAGE_B;
        int k0 = kt * 64;
#pragma unroll
        for (int it = 0; it < 2; it++) {
            int idx = t + it * 256;
            int r = idx >> 3, seg = idx & 7;
            size_t srcK = (tok0 + k0 + r) * N_QKV + D_MODEL + h * HEAD_DIM + seg * 8;
            uint32_t dst = (r * AT_STR + seg * 8) * 2;
            cp_async16(stg + 0 * KV_TILE_B + dst, qkvh + srcK);
            cp_async16(stg + 1 * KV_TILE_B + dst, qkvh + srcK + D_MODEL);
        }
        asm volatile("cp.async.commit_group;" ::: "memory");
    };

    load_kv(0, 0);
    asm volatile("cp.async.wait_group 1;" ::: "memory");
    __syncthreads();

    float M0 = -1e30f, M1 = -1e30f, L0 = 0.f, L1 = 0.f;
    float o[8][4];
#pragma unroll
    for (int i = 0; i < 8; i++)
#pragma unroll
        for (int j = 0; j < 4; j++) o[i][j] = 0.f;

    const uint32_t a_off = ((w * 16 + (l & 15)) * AT_STR + (l >> 4) * 8) * 2;
    const uint32_t kb_off = (((l & 7) + ((l >> 4) << 3)) * AT_STR +
                             ((l >> 3) & 1) * 8) * 2;
    const uint32_t vb_off = ((l & 15) * AT_STR + (l >> 4) * 8) * 2;
    const int row0 = q0 + w * 16 + (l >> 2);
    const int colq = (l & 3) * 2;
    const int NT = 2 * qt + 2;

    for (int kt = 0; kt < NT; kt++) {
        if (kt + 1 < NT) {
            load_kv(kt + 1, (kt + 1) & 1);
            asm volatile("cp.async.wait_group 1;" ::: "memory");
        } else {
            asm volatile("cp.async.wait_group 0;" ::: "memory");
        }
        __syncthreads();
        const uint32_t stg = sb + ST0 + (kt & 1) * KV_STAGE_B;

        float sacc[8][4];
#pragma unroll
        for (int i = 0; i < 8; i++)
#pragma unroll
            for (int j = 0; j < 4; j++) sacc[i][j] = 0.f;

#pragma unroll
        for (int ks = 0; ks < 4; ks++) {
            uint32_t qh[4], ql[4];
            ldsm_x4(qh, sb + QH + a_off + ks * 32);
            ldsm_x4(ql, sb + QL + a_off + ks * 32);
#pragma unroll
            for (int np = 0; np < 4; np++) {
                uint32_t bh[4];
                uint32_t o2 = (np * 16 * AT_STR + ks * 16) * 2;
                ldsm_x4(bh, stg + 0 * KV_TILE_B + kb_off + o2);
                mma16816(sacc[2 * np], qh, bh);
                mma16816(sacc[2 * np], ql, bh);
                mma16816(sacc[2 * np + 1], qh, bh + 2);
                mma16816(sacc[2 * np + 1], ql, bh + 2);
            }
        }

        const int k0 = kt * 64;
        const bool dm = (kt >= 2 * qt);
#pragma unroll
        for (int nt = 0; nt < 8; nt++) {
            int colb = k0 + nt * 8 + colq;
#pragma unroll
            for (int j = 0; j < 4; j++) {
                float v = sacc[nt][j] * 0.125f;
                if (dm && (colb + (j & 1)) > (row0 + (j >> 1) * 8)) v = -1e30f;
                sacc[nt][j] = v;
            }
        }

        float m0 = -1e30f, m1 = -1e30f;
#pragma unroll
        for (int nt = 0; nt < 8; nt++) {
            m0 = fmaxf(m0, fmaxf(sacc[nt][0], sacc[nt][1]));
            m1 = fmaxf(m1, fmaxf(sacc[nt][2], sacc[nt][3]));
        }
        m0 = fmaxf(m0, __shfl_xor_sync(~0u, m0, 1));
        m0 = fmaxf(m0, __shfl_xor_sync(~0u, m0, 2));
        m1 = fmaxf(m1, __shfl_xor_sync(~0u, m1, 1));
        m1 = fmaxf(m1, __shfl_xor_sync(~0u, m1, 2));
        float Mn0 = fmaxf(M0, m0), Mn1 = fmaxf(M1, m1);
        float f0 = __expf(M0 - Mn0), f1 = __expf(M1 - Mn1);
        float rs0 = 0.f, rs1 = 0.f;
#pragma unroll
        for (int nt = 0; nt < 8; nt++) {
            sacc[nt][0] = __expf(sacc[nt][0] - Mn0);
            sacc[nt][1] = __expf(sacc[nt][1] - Mn0);
            sacc[nt][2] = __expf(sacc[nt][2] - Mn1);
            sacc[nt][3] = __expf(sacc[nt][3] - Mn1);
            rs0 += sacc[nt][0] + sacc[nt][1];
            rs1 += sacc[nt][2] + sacc[nt][3];
        }
        rs0 += __shfl_xor_sync(~0u, rs0, 1);
        rs0 += __shfl_xor_sync(~0u, rs0, 2);
        rs1 += __shfl_xor_sync(~0u, rs1, 1);
        rs1 += __shfl_xor_sync(~0u, rs1, 2);
        L0 = L0 * f0 + rs0; L1 = L1 * f1 + rs1;
        M0 = Mn0; M1 = Mn1;

#pragma unroll
        for (int nt = 0; nt < 8; nt++) {
            o[nt][0] *= f0; o[nt][1] *= f0;
            o[nt][2] *= f1; o[nt][3] *= f1;
        }

#pragma unroll
        for (int ks = 0; ks < 4; ks++) {
            uint32_t ph[4], pl[4];
            split2h(sacc[2 * ks][0], sacc[2 * ks][1], ph[0], pl[0]);
            split2h(sacc[2 * ks][2], sacc[2 * ks][3], ph[1], pl[1]);
            split2h(sacc[2 * ks + 1][0], sacc[2 * ks + 1][1], ph[2], pl[2]);
            split2h(sacc[2 * ks + 1][2], sacc[2 * ks + 1][3], ph[3], pl[3]);
#pragma unroll
            for (int np = 0; np < 4; np++) {
                uint32_t vh[4];
                uint32_t o2 = (ks * 16 * AT_STR + np * 16) * 2;
                ldsm_x4_t(vh, stg + 1 * KV_TILE_B + vb_off + o2);
                mma16816(o[2 * np], ph, vh);
                mma16816(o[2 * np], pl, vh);
                mma16816(o[2 * np + 1], ph, vh + 2);
                mma16816(o[2 * np + 1], pl, vh + 2);
            }
        }
        __syncthreads();
    }

    const float i0 = 1.f / L0, i1 = 1.f / L1;
#pragma unroll
    for (int nt = 0; nt < 8; nt++) {
        int col = h * HEAD_DIM + nt * 8 + colq;
        uint32_t h0, l0r, h1, l1r;
        split2h(o[nt][0] * i0, o[nt][1] * i0, h0, l0r);
        split2h(o[nt][2] * i1, o[nt][3] * i1, h1, l1r);
        size_t r0 = (tok0 + row0) * D_MODEL + col;
        size_t r1 = (tok0 + row0 + 8) * D_MODEL + col;
        *(uint32_t*)(ah + r0) = h0;
        *(uint32_t*)(al + r0) = l0r;
        *(uint32_t*)(ah + r1) = h1;
        *(uint32_t*)(al + r1) = l1r;
    }
}

// ---------------------------------------------------------------------------
extern "C" void kernel_launch(void* const* d_in, const int* in_sizes, int n_in,
                              void* d_out, int out_size)
{
    const float* x     = (const float*)d_in[0];
    const float* qkv_w = (const float*)d_in[1];
    const float* qkv_b = (const float*)d_in[2];
    const float* out_w = (const float*)d_in[3];
    const float* out_b = (const float*)d_in[4];
    float* out = (float*)d_out;

    __half *qkvh, *qkvl, *xh, *xl, *wq, *wo, *ah, *al;
    cudaGetSymbolAddress((void**)&qkvh, g_qkvh);
    cudaGetSymbolAddress((void**)&qkvl, g_qkvl);
    cudaGetSymbolAddress((void**)&xh, g_xh);
    cudaGetSymbolAddress((void**)&xl, g_xl);
    cudaGetSymbolAddress((void**)&wq, g_wq);
    cudaGetSymbolAddress((void**)&wo, g_wo);
    cudaGetSymbolAddress((void**)&ah, g_ah);
    cudaGetSymbolAddress((void**)&al, g_al);

    cudaFuncSetAttribute(gemm_mma_split, cudaFuncAttributeMaxDynamicSharedMemorySize,
                         GEMM_SMEM);
    cudaFuncSetAttribute(flash_attn_mma, cudaFuncAttributeMaxDynamicSharedMemorySize,
                         ATT_SMEM);

    int n2x = M_TOT * D_MODEL / 2;
    int n2q = N_QKV * D_MODEL / 2;
    int n2o = D_MODEL * D_MODEL / 2;
    split_fp16<<<(n2x + 255) / 256, 256>>>((const float2*)x,
        (__half2*)xh, (__half2*)xl, n2x);
    round_fp16<<<(n2q + 255) / 256, 256>>>((const float2*)qkv_w, (__half2*)wq, n2q);
    round_fp16<<<(n2o + 255) / 256, 256>>>((const float2*)out_w, (__half2*)wo, n2o);

    // 1) QKV projection -> split fp16 output
    gemm_mma_split<<<dim3(N_QKV / 128, M_TOT / 128), 256, GEMM_SMEM>>>(
        xh, xl, wq, qkv_b, nullptr, qkvh, qkvl, N_QKV, D_MODEL, 1);

    // 2) Tensor-core causal flash attention -> split fp16 output
    flash_attn_mma<<<dim3(SEQ / 128, N_HEADS, BATCH), 256, ATT_SMEM>>>(
        qkvh, qkvl, ah, al);

    // 3) Output projection -> fp32 final
    gemm_mma_split<<<dim3(D_MODEL / 128, M_TOT / 128), 256, GEMM_SMEM>>>(
        ah, al, wo, out_b, out, nullptr, nullptr, D_MODEL, D_MODEL, 0);
}

// round 7
// speedup vs baseline: 4.9502x; 1.1909x over previous
#include <cuda_runtime.h>
#include <cuda_fp16.h>
#include <math.h>
#include <float.h>
#include <cstdint>

#define D_MODEL  1024
#define N_HEADS  16
#define HEAD_DIM 64
#define BATCH    2
#define SEQ      2048
#define M_TOT    (BATCH * SEQ)     // 4096
#define N_QKV    (3 * D_MODEL)     // 3072

// ---------------- scratch (allocation-free rule: __device__ globals) --------
__device__ __half g_qkv[(size_t)M_TOT * N_QKV];    // fp16 qkv (hi only)
__device__ __half g_xh[(size_t)M_TOT * D_MODEL];
__device__ __half g_xl[(size_t)M_TOT * D_MODEL];
__device__ __half g_wq[(size_t)N_QKV * D_MODEL];
__device__ __half g_wo[(size_t)D_MODEL * D_MODEL];
__device__ __half g_ah[(size_t)M_TOT * D_MODEL];
__device__ __half g_al[(size_t)M_TOT * D_MODEL];

// ---------------- helpers ---------------------------------------------------
__device__ __forceinline__ uint32_t smem_u32(const void* p) {
    uint32_t a;
    asm("{ .reg .u64 t; cvta.to.shared.u64 t, %1; cvt.u32.u64 %0, t; }"
        : "=r"(a) : "l"(p));
    return a;
}
__device__ __forceinline__ void cp_async16(uint32_t dst, const void* src) {
    asm volatile("cp.async.cg.shared.global [%0], [%1], 16;" :: "r"(dst), "l"(src)
                 : "memory");
}
__device__ __forceinline__ void ldsm_x4(uint32_t* r, uint32_t addr) {
    asm volatile("ldmatrix.sync.aligned.m8n8.x4.shared.b16 {%0,%1,%2,%3}, [%4];"
        : "=r"(r[0]), "=r"(r[1]), "=r"(r[2]), "=r"(r[3]) : "r"(addr));
}
__device__ __forceinline__ void ldsm_x4_t(uint32_t* r, uint32_t addr) {
    asm volatile("ldmatrix.sync.aligned.m8n8.x4.trans.shared.b16 {%0,%1,%2,%3}, [%4];"
        : "=r"(r[0]), "=r"(r[1]), "=r"(r[2]), "=r"(r[3]) : "r"(addr));
}
__device__ __forceinline__ void mma16816(float* c, const uint32_t* a, const uint32_t* b) {
    asm volatile("mma.sync.aligned.m16n8k16.row.col.f32.f16.f16.f32 "
        "{%0,%1,%2,%3}, {%4,%5,%6,%7}, {%8,%9}, {%0,%1,%2,%3};"
        : "+f"(c[0]), "+f"(c[1]), "+f"(c[2]), "+f"(c[3])
        : "r"(a[0]), "r"(a[1]), "r"(a[2]), "r"(a[3]), "r"(b[0]), "r"(b[1]));
}
__device__ __forceinline__ void split2h(float a, float b, uint32_t& hi, uint32_t& lo) {
    __half2 h = __floats2half2_rn(a, b);
    float2 hf = __half22float2(h);
    __half2 l = __floats2half2_rn(a - hf.x, b - hf.y);
    hi = *(uint32_t*)&h; lo = *(uint32_t*)&l;
}
__device__ __forceinline__ uint32_t pack2h(float a, float b) {
    __half2 h = __floats2half2_rn(a, b);
    return *(uint32_t*)&h;
}

// ---------------- fp32 -> fp16 (hi, lo) split / round -----------------------
__global__ void __launch_bounds__(256) split_fp16(
    const float2* __restrict__ in, __half2* __restrict__ hi,
    __half2* __restrict__ lo, int n2)
{
    int i = blockIdx.x * blockDim.x + threadIdx.x;
    if (i < n2) {
        float2 v = in[i];
        __half2 h = __floats2half2_rn(v.x, v.y);
        float2 hf = __half22float2(h);
        hi[i] = h;
        lo[i] = __floats2half2_rn(v.x - hf.x, v.y - hf.y);
    }
}
__global__ void __launch_bounds__(256) round_fp16(
    const float2* __restrict__ in, __half2* __restrict__ out, int n2)
{
    int i = blockIdx.x * blockDim.x + threadIdx.x;
    if (i < n2) {
        float2 v = in[i];
        out[i] = __floats2half2_rn(v.x, v.y);
    }
}

// ---------------- mma.sync fp16 2-term GEMM, BK=64, 2-stage -----------------
// C[m,n] = sum_k A[m,k]*B[n,k] + bias[n].  A K-major (hi,lo) fp16, B fp16.
// mode: 0 = fp32 C, 1 = split (Ch,Cl), 2 = hi-only (Ch)
#define GTILE_B  (128 * 128)         // 16384 B per operand tile (BK=64)
#define GSTAGE_B (3 * GTILE_B)       // Ah, Al, B = 49152 B
#define GEMM_SMEM (2 * GSTAGE_B)     // 98304 B

__global__ void __launch_bounds__(256, 2) gemm_mma_split(
    const __half* __restrict__ Ah, const __half* __restrict__ Al,
    const __half* __restrict__ Bh,
    const float* __restrict__ bias, float* __restrict__ C,
    __half* __restrict__ Ch, __half* __restrict__ Cl,
    int N, int K, int mode)
{
    extern __shared__ char smem[];
    const uint32_t sbase = smem_u32(smem);
    const int t = threadIdx.x, lane = t & 31, wid = t >> 5;
    const int wm0 = (wid & 3) * 32, wn0 = (wid >> 2) * 64;
    const int m0 = blockIdx.y * 128, n0 = blockIdx.x * 128;

    const __half* srcs[3] = {Ah, Al, Bh};

    auto load = [&](int c, int st) {
        uint32_t stg = sbase + st * GSTAGE_B;
#pragma unroll
        for (int i = 0; i < 12; i++) {
            int idx = t + i * 256;            // 0..3071: [tile 3][row 128][seg 8]
            int tile = idx >> 10;
            int r = (idx >> 3) & 127;
            int s = idx & 7;
            int row0 = (tile < 2) ? m0 : n0;
            uint32_t sw = r * 128 + (((s ^ (r & 7)) & 7) << 4);
            cp_async16(stg + tile * GTILE_B + sw,
                       srcs[tile] + (size_t)(row0 + r) * K + c * 64 + s * 8);
        }
        asm volatile("cp.async.commit_group;" ::: "memory");
    };

    float acc[16][4];
#pragma unroll
    for (int i = 0; i < 16; i++)
#pragma unroll
        for (int j = 0; j < 4; j++) acc[i][j] = 0.0f;

    const int l15 = lane & 15;
    const uint32_t arx = l15 & 7;
    uint32_t ar128[2];
    ar128[0] = (wm0 + l15) * 128;
    ar128[1] = (wm0 + 16 + l15) * 128;
    const uint32_t brbase = wn0 + ((lane >> 4) << 3) + (lane & 7);
    const uint32_t brx = brbase & 7;
    const uint32_t bsel = (lane >> 3) & 1;

    const int NC = K / 64;
    load(0, 0);

    for (int c = 0; c < NC; c++) {
        if (c + 1 < NC) {
            load(c + 1, (c + 1) & 1);
            asm volatile("cp.async.wait_group 1;" ::: "memory");
        } else {
            asm volatile("cp.async.wait_group 0;" ::: "memory");
        }
        __syncthreads();

        const uint32_t stg = sbase + (c & 1) * GSTAGE_B;
#pragma unroll
        for (int kk = 0; kk < 4; kk++) {
            uint32_t aHf[2][4], aLf[2][4];
            const uint32_t sA = kk * 2 + (lane >> 4);
#pragma unroll
            for (int mt = 0; mt < 2; mt++) {
                uint32_t col = ((sA ^ arx) & 7) << 4;
                ldsm_x4(aHf[mt], stg + 0 * GTILE_B + ar128[mt] + col);
                ldsm_x4(aLf[mt], stg + 1 * GTILE_B + ar128[mt] + col);
            }
            const uint32_t sB = kk * 2 + bsel;
            const uint32_t bcol = ((sB ^ brx) & 7) << 4;
#pragma unroll
            for (int nt2 = 0; nt2 < 4; nt2++) {
                uint32_t bh[4];
                uint32_t baddr = (brbase + nt2 * 16) * 128 + bcol;
                ldsm_x4(bh, stg + 2 * GTILE_B + baddr);
#pragma unroll
                for (int mt = 0; mt < 2; mt++) {
                    float* c0 = acc[mt * 8 + nt2 * 2];
                    float* c1 = acc[mt * 8 + nt2 * 2 + 1];
                    mma16816(c0, aHf[mt], bh);
                    mma16816(c0, aLf[mt], bh);
                    mma16816(c1, aHf[mt], bh + 2);
                    mma16816(c1, aLf[mt], bh + 2);
                }
            }
        }
        __syncthreads();
    }

    const int r0 = m0 + wm0 + (lane >> 2);
    const int c0l = (lane & 3) * 2;
#pragma unroll
    for (int mt = 0; mt < 2; mt++)
#pragma unroll
        for (int nt = 0; nt < 8; nt++) {
            const float* c4 = acc[mt * 8 + nt];
            int row = r0 + mt * 16;
            int col = n0 + wn0 + nt * 8 + c0l;
            float2 bi = *(const float2*)(bias + col);
            float v0 = c4[0] + bi.x, v1 = c4[1] + bi.y;
            float v2 = c4[2] + bi.x, v3 = c4[3] + bi.y;
            if (mode == 0) {
                *(float2*)(C + (size_t)row * N + col) = make_float2(v0, v1);
                *(float2*)(C + (size_t)(row + 8) * N + col) = make_float2(v2, v3);
            } else if (mode == 2) {
                *(uint32_t*)(Ch + (size_t)row * N + col) = pack2h(v0, v1);
                *(uint32_t*)(Ch + (size_t)(row + 8) * N + col) = pack2h(v2, v3);
            } else {
                uint32_t h0, l0, h1, l1;
                split2h(v0, v1, h0, l0);
                split2h(v2, v3, h1, l1);
                *(uint32_t*)(Ch + (size_t)row * N + col) = h0;
                *(uint32_t*)(Cl + (size_t)row * N + col) = l0;
                *(uint32_t*)(Ch + (size_t)(row + 8) * N + col) = h1;
                *(uint32_t*)(Cl + (size_t)(row + 8) * N + col) = l1;
            }
        }
}

// ---------------------------------------------------------------------------
// Tensor-core causal flash attention, single fp16 operands (Q,K,P,V).
// Output written as split fp16 (for accurate out-projection A-side).
// ---------------------------------------------------------------------------
#define AT_STR 72                          // smem stride in fp16 (144 B)
#define Q_TILE_B (128 * AT_STR * 2)        // 18432
#define KV_TILE_B (64 * AT_STR * 2)        // 9216
#define KV_STAGE_B (2 * KV_TILE_B)         // K, V
#define ATT_SMEM (Q_TILE_B + 2 * KV_STAGE_B)  // 55296

__global__ void __launch_bounds__(256, 2) flash_attn_mma(
    const __half* __restrict__ qkv,
    __half* __restrict__ ah, __half* __restrict__ al)
{
    extern __shared__ char smem[];
    const uint32_t sb = smem_u32(smem);
    const uint32_t QH = 0, ST0 = Q_TILE_B;
    const int t = threadIdx.x, l = t & 31, w = t >> 5;
    const int qt = (int)(gridDim.x - 1 - blockIdx.x);   // heavy tiles first
    const int h = blockIdx.y, b = blockIdx.z;
    const int q0 = qt * 128;
    const size_t tok0 = (size_t)b * SEQ;

#pragma unroll
    for (int it = 0; it < 4; it++) {
        int idx = t + it * 256;             // 0..1023 over [128 r][8 seg]
        int r = idx >> 3, seg = idx & 7;
        size_t src = (tok0 + q0 + r) * N_QKV + h * HEAD_DIM + seg * 8;
        cp_async16(sb + QH + (r * AT_STR + seg * 8) * 2, qkv + src);
    }
    asm volatile("cp.async.commit_group;" ::: "memory");

    auto load_kv = [&](int kt, int s) {
        uint32_t stg = sb + ST0 + s * KV_STAGE_B;
        int k0 = kt * 64;
#pragma unroll
        for (int it = 0; it < 2; it++) {
            int idx = t + it * 256;         // 0..511 over [64 r][8 seg]
            int r = idx >> 3, seg = idx & 7;
            size_t srcK = (tok0 + k0 + r) * N_QKV + D_MODEL + h * HEAD_DIM + seg * 8;
            uint32_t dst = (r * AT_STR + seg * 8) * 2;
            cp_async16(stg + 0 * KV_TILE_B + dst, qkv + srcK);
            cp_async16(stg + 1 * KV_TILE_B + dst, qkv + srcK + D_MODEL);
        }
        asm volatile("cp.async.commit_group;" ::: "memory");
    };

    load_kv(0, 0);
    asm volatile("cp.async.wait_group 1;" ::: "memory");   // Q ready
    __syncthreads();

    // hoist Q fragments (hi only)
    uint32_t qfh[4][4];
    const uint32_t a_off = ((w * 16 + (l & 15)) * AT_STR + (l >> 4) * 8) * 2;
#pragma unroll
    for (int ks = 0; ks < 4; ks++)
        ldsm_x4(qfh[ks], sb + QH + a_off + ks * 32);

    float M0 = -1e30f, M1 = -1e30f, L0 = 0.f, L1 = 0.f;
    float o[8][4];
#pragma unroll
    for (int i = 0; i < 8; i++)
#pragma unroll
        for (int j = 0; j < 4; j++) o[i][j] = 0.f;

    const uint32_t kb_off = (((l & 7) + ((l >> 4) << 3)) * AT_STR +
                             ((l >> 3) & 1) * 8) * 2;
    const uint32_t vb_off = ((l & 15) * AT_STR + (l >> 4) * 8) * 2;
    const int row0 = q0 + w * 16 + (l >> 2);
    const int colq = (l & 3) * 2;
    const int NT = 2 * qt + 2;

    for (int kt = 0; kt < NT; kt++) {
        if (kt + 1 < NT) {
            load_kv(kt + 1, (kt + 1) & 1);
            asm volatile("cp.async.wait_group 1;" ::: "memory");
        } else {
            asm volatile("cp.async.wait_group 0;" ::: "memory");
        }
        __syncthreads();
        const uint32_t stg = sb + ST0 + (kt & 1) * KV_STAGE_B;

        float sacc[8][4];
#pragma unroll
        for (int i = 0; i < 8; i++)
#pragma unroll
            for (int j = 0; j < 4; j++) sacc[i][j] = 0.f;

#pragma unroll
        for (int ks = 0; ks < 4; ks++) {
#pragma unroll
            for (int np = 0; np < 4; np++) {
                uint32_t bh[4];
                uint32_t o2 = (np * 16 * AT_STR + ks * 16) * 2;
                ldsm_x4(bh, stg + 0 * KV_TILE_B + kb_off + o2);
                mma16816(sacc[2 * np], qfh[ks], bh);
                mma16816(sacc[2 * np + 1], qfh[ks], bh + 2);
            }
        }

        const int k0 = kt * 64;
        const bool dm = (kt >= 2 * qt);
#pragma unroll
        for (int nt = 0; nt < 8; nt++) {
            int colb = k0 + nt * 8 + colq;
#pragma unroll
            for (int j = 0; j < 4; j++) {
                float v = sacc[nt][j] * 0.125f;
                if (dm && (colb + (j & 1)) > (row0 + (j >> 1) * 8)) v = -1e30f;
                sacc[nt][j] = v;
            }
        }

        float m0 = -1e30f, m1 = -1e30f;
#pragma unroll
        for (int nt = 0; nt < 8; nt++) {
            m0 = fmaxf(m0, fmaxf(sacc[nt][0], sacc[nt][1]));
            m1 = fmaxf(m1, fmaxf(sacc[nt][2], sacc[nt][3]));
        }
        m0 = fmaxf(m0, __shfl_xor_sync(~0u, m0, 1));
        m0 = fmaxf(m0, __shfl_xor_sync(~0u, m0, 2));
        m1 = fmaxf(m1, __shfl_xor_sync(~0u, m1, 1));
        m1 = fmaxf(m1, __shfl_xor_sync(~0u, m1, 2));
        float Mn0 = fmaxf(M0, m0), Mn1 = fmaxf(M1, m1);
        float f0 = __expf(M0 - Mn0), f1 = __expf(M1 - Mn1);
        float rs0 = 0.f, rs1 = 0.f;
#pragma unroll
        for (int nt = 0; nt < 8; nt++) {
            sacc[nt][0] = __expf(sacc[nt][0] - Mn0);
            sacc[nt][1] = __expf(sacc[nt][1] - Mn0);
            sacc[nt][2] = __expf(sacc[nt][2] - Mn1);
            sacc[nt][3] = __expf(sacc[nt][3] - Mn1);
            rs0 += sacc[nt][0] + sacc[nt][1];
            rs1 += sacc[nt][2] + sacc[nt][3];
        }
        rs0 += __shfl_xor_sync(~0u, rs0, 1);
        rs0 += __shfl_xor_sync(~0u, rs0, 2);
        rs1 += __shfl_xor_sync(~0u, rs1, 1);
        rs1 += __shfl_xor_sync(~0u, rs1, 2);
        L0 = L0 * f0 + rs0; L1 = L1 * f1 + rs1;
        M0 = Mn0; M1 = Mn1;

#pragma unroll
        for (int nt = 0; nt < 8; nt++) {
            o[nt][0] *= f0; o[nt][1] *= f0;
            o[nt][2] *= f1; o[nt][3] *= f1;
        }

        // O += P V  (P rounded to single fp16)
#pragma unroll
        for (int ks = 0; ks < 4; ks++) {
            uint32_t ph[4];
            ph[0] = pack2h(sacc[2 * ks][0], sacc[2 * ks][1]);
            ph[1] = pack2h(sacc[2 * ks][2], sacc[2 * ks][3]);
            ph[2] = pack2h(sacc[2 * ks + 1][0], sacc[2 * ks + 1][1]);
            ph[3] = pack2h(sacc[2 * ks + 1][2], sacc[2 * ks + 1][3]);
#pragma unroll
            for (int np = 0; np < 4; np++) {
                uint32_t vh[4];
                uint32_t o2 = (ks * 16 * AT_STR + np * 16) * 2;
                ldsm_x4_t(vh, stg + 1 * KV_TILE_B + vb_off + o2);
                mma16816(o[2 * np], ph, vh);
                mma16816(o[2 * np + 1], ph, vh + 2);
            }
        }
        __syncthreads();
    }

    const float i0 = 1.f / L0, i1 = 1.f / L1;
#pragma unroll
    for (int nt = 0; nt < 8; nt++) {
        int col = h * HEAD_DIM + nt * 8 + colq;
        uint32_t h0, l0r, h1, l1r;
        split2h(o[nt][0] * i0, o[nt][1] * i0, h0, l0r);
        split2h(o[nt][2] * i1, o[nt][3] * i1, h1, l1r);
        size_t r0 = (tok0 + row0) * D_MODEL + col;
        size_t r1 = (tok0 + row0 + 8) * D_MODEL + col;
        *(uint32_t*)(ah + r0) = h0;
        *(uint32_t*)(al + r0) = l0r;
        *(uint32_t*)(ah + r1) = h1;
        *(uint32_t*)(al + r1) = l1r;
    }
}

// ---------------------------------------------------------------------------
extern "C" void kernel_launch(void* const* d_in, const int* in_sizes, int n_in,
                              void* d_out, int out_size)
{
    const float* x     = (const float*)d_in[0];
    const float* qkv_w = (const float*)d_in[1];
    const float* qkv_b = (const float*)d_in[2];
    const float* out_w = (const float*)d_in[3];
    const float* out_b = (const float*)d_in[4];
    float* out = (float*)d_out;

    __half *qkv, *xh, *xl, *wq, *wo, *ah, *al;
    cudaGetSymbolAddress((void**)&qkv, g_qkv);
    cudaGetSymbolAddress((void**)&xh, g_xh);
    cudaGetSymbolAddress((void**)&xl, g_xl);
    cudaGetSymbolAddress((void**)&wq, g_wq);
    cudaGetSymbolAddress((void**)&wo, g_wo);
    cudaGetSymbolAddress((void**)&ah, g_ah);
    cudaGetSymbolAddress((void**)&al, g_al);

    cudaFuncSetAttribute(gemm_mma_split, cudaFuncAttributeMaxDynamicSharedMemorySize,
                         GEMM_SMEM);
    cudaFuncSetAttribute(flash_attn_mma, cudaFuncAttributeMaxDynamicSharedMemorySize,
                         ATT_SMEM);

    int n2x = M_TOT * D_MODEL / 2;
    int n2q = N_QKV * D_MODEL / 2;
    int n2o = D_MODEL * D_MODEL / 2;
    split_fp16<<<(n2x + 255) / 256, 256>>>((const float2*)x,
        (__half2*)xh, (__half2*)xl, n2x);
    round_fp16<<<(n2q + 255) / 256, 256>>>((const float2*)qkv_w, (__half2*)wq, n2q);
    round_fp16<<<(n2o + 255) / 256, 256>>>((const float2*)out_w, (__half2*)wo, n2o);

    // 1) QKV projection -> fp16 (hi only)
    gemm_mma_split<<<dim3(N_QKV / 128, M_TOT / 128), 256, GEMM_SMEM>>>(
        xh, xl, wq, qkv_b, nullptr, qkv, nullptr, N_QKV, D_MODEL, 2);

    // 2) Tensor-core causal flash attention -> split fp16 output
    flash_attn_mma<<<dim3(SEQ / 128, N_HEADS, BATCH), 256, ATT_SMEM>>>(
        qkv, ah, al);

    // 3) Output projection -> fp32 final
    gemm_mma_split<<<dim3(D_MODEL / 128, M_TOT / 128), 256, GEMM_SMEM>>>(
        ah, al, wo, out_b, out, nullptr, nullptr, D_MODEL, D_MODEL, 0);
}

// round 8
// speedup vs baseline: 6.7050x; 1.3545x over previous
#include <cuda_runtime.h>
#include <cuda_fp16.h>
#include <math.h>
#include <float.h>
#include <cstdint>

#define D_MODEL  1024
#define N_HEADS  16
#define HEAD_DIM 64
#define BATCH    2
#define SEQ      2048
#define M_TOT    (BATCH * SEQ)     // 4096
#define N_QKV    (3 * D_MODEL)     // 3072

// ---------------- scratch (allocation-free rule: __device__ globals) --------
__device__ __half g_qkv[(size_t)M_TOT * N_QKV];    // fp16 qkv
__device__ __half g_x[(size_t)M_TOT * D_MODEL];
__device__ __half g_wq[(size_t)N_QKV * D_MODEL];
__device__ __half g_wo[(size_t)D_MODEL * D_MODEL];
__device__ __half g_att[(size_t)M_TOT * D_MODEL];

// ---------------- helpers ---------------------------------------------------
__device__ __forceinline__ uint32_t smem_u32(const void* p) {
    uint32_t a;
    asm("{ .reg .u64 t; cvta.to.shared.u64 t, %1; cvt.u32.u64 %0, t; }"
        : "=r"(a) : "l"(p));
    return a;
}
__device__ __forceinline__ void cp_async16(uint32_t dst, const void* src) {
    asm volatile("cp.async.cg.shared.global [%0], [%1], 16;" :: "r"(dst), "l"(src)
                 : "memory");
}
__device__ __forceinline__ void ldsm_x4(uint32_t* r, uint32_t addr) {
    asm volatile("ldmatrix.sync.aligned.m8n8.x4.shared.b16 {%0,%1,%2,%3}, [%4];"
        : "=r"(r[0]), "=r"(r[1]), "=r"(r[2]), "=r"(r[3]) : "r"(addr));
}
__device__ __forceinline__ void ldsm_x4_t(uint32_t* r, uint32_t addr) {
    asm volatile("ldmatrix.sync.aligned.m8n8.x4.trans.shared.b16 {%0,%1,%2,%3}, [%4];"
        : "=r"(r[0]), "=r"(r[1]), "=r"(r[2]), "=r"(r[3]) : "r"(addr));
}
__device__ __forceinline__ void mma16816(float* c, const uint32_t* a, const uint32_t* b) {
    asm volatile("mma.sync.aligned.m16n8k16.row.col.f32.f16.f16.f32 "
        "{%0,%1,%2,%3}, {%4,%5,%6,%7}, {%8,%9}, {%0,%1,%2,%3};"
        : "+f"(c[0]), "+f"(c[1]), "+f"(c[2]), "+f"(c[3])
        : "r"(a[0]), "r"(a[1]), "r"(a[2]), "r"(a[3]), "r"(b[0]), "r"(b[1]));
}
__device__ __forceinline__ uint32_t pack2h(float a, float b) {
    __half2 h = __floats2half2_rn(a, b);
    return *(uint32_t*)&h;
}

// ---------------- fp32 -> fp16 round ----------------------------------------
__global__ void __launch_bounds__(256) round_fp16(
    const float2* __restrict__ in, __half2* __restrict__ out, int n2)
{
    int i = blockIdx.x * blockDim.x + threadIdx.x;
    if (i < n2) {
        float2 v = in[i];
        out[i] = __floats2half2_rn(v.x, v.y);
    }
}

// ---------------- mma.sync fp16 GEMM, BK=64, 3-stage ring -------------------
// C[m,n] = sum_k A[m,k]*B[n,k] + bias[n].  A,B K-major fp16.
// mode: 0 = fp32 C, 2 = fp16 Ch
#define GTILE_B  (128 * 128)         // 16384 B per operand tile (BK=64)
#define GSTAGE_B (2 * GTILE_B)       // A, B = 32768 B
#define GEMM_SMEM (3 * GSTAGE_B)     // 98304 B

__global__ void __launch_bounds__(256, 2) gemm_mma(
    const __half* __restrict__ A, const __half* __restrict__ B,
    const float* __restrict__ bias, float* __restrict__ C,
    __half* __restrict__ Ch, int N, int K, int mode)
{
    extern __shared__ char smem[];
    const uint32_t sbase = smem_u32(smem);
    const int t = threadIdx.x, lane = t & 31, wid = t >> 5;
    const int wm0 = (wid & 3) * 32, wn0 = (wid >> 2) * 64;
    const int m0 = blockIdx.y * 128, n0 = blockIdx.x * 128;

    auto load = [&](int c, int st) {
        uint32_t stg = sbase + st * GSTAGE_B;
#pragma unroll
        for (int i = 0; i < 8; i++) {
            int idx = t + i * 256;            // 0..2047: [tile 2][row 128][seg 8]
            int tile = idx >> 10;
            int r = (idx >> 3) & 127;
            int s = idx & 7;
            int row0 = tile ? n0 : m0;
            const __half* src = tile ? B : A;
            uint32_t sw = r * 128 + (((s ^ (r & 7)) & 7) << 4);
            cp_async16(stg + tile * GTILE_B + sw,
                       src + (size_t)(row0 + r) * K + c * 64 + s * 8);
        }
        asm volatile("cp.async.commit_group;" ::: "memory");
    };

    float acc[16][4];
#pragma unroll
    for (int i = 0; i < 16; i++)
#pragma unroll
        for (int j = 0; j < 4; j++) acc[i][j] = 0.0f;

    const int l15 = lane & 15;
    const uint32_t arx = l15 & 7;
    uint32_t ar128[2];
    ar128[0] = (wm0 + l15) * 128;
    ar128[1] = (wm0 + 16 + l15) * 128;
    const uint32_t brbase = wn0 + ((lane >> 4) << 3) + (lane & 7);
    const uint32_t brx = brbase & 7;
    const uint32_t bsel = (lane >> 3) & 1;

    const int NC = K / 64;
    load(0, 0);
    load(1, 1);

    for (int c = 0; c < NC; c++) {
        if (c + 1 < NC)
            asm volatile("cp.async.wait_group 1;" ::: "memory");
        else
            asm volatile("cp.async.wait_group 0;" ::: "memory");
        __syncthreads();
        if (c + 2 < NC) {
            int st2 = c + 2;
            st2 -= (st2 / 3) * 3;
            load(c + 2, st2);
        }

        int stidx = c; stidx -= (stidx / 3) * 3;
        const uint32_t stg = sbase + stidx * GSTAGE_B;
#pragma unroll
        for (int kk = 0; kk < 4; kk++) {
            uint32_t af[2][4];
            const uint32_t sA = kk * 2 + (lane >> 4);
#pragma unroll
            for (int mt = 0; mt < 2; mt++) {
                uint32_t col = ((sA ^ arx) & 7) << 4;
                ldsm_x4(af[mt], stg + ar128[mt] + col);
            }
            const uint32_t sB = kk * 2 + bsel;
            const uint32_t bcol = ((sB ^ brx) & 7) << 4;
#pragma unroll
            for (int nt2 = 0; nt2 < 4; nt2++) {
                uint32_t bh[4];
                uint32_t baddr = (brbase + nt2 * 16) * 128 + bcol;
                ldsm_x4(bh, stg + GTILE_B + baddr);
#pragma unroll
                for (int mt = 0; mt < 2; mt++) {
                    mma16816(acc[mt * 8 + nt2 * 2], af[mt], bh);
                    mma16816(acc[mt * 8 + nt2 * 2 + 1], af[mt], bh + 2);
                }
            }
        }
    }

    const int r0 = m0 + wm0 + (lane >> 2);
    const int c0l = (lane & 3) * 2;
#pragma unroll
    for (int mt = 0; mt < 2; mt++)
#pragma unroll
        for (int nt = 0; nt < 8; nt++) {
            const float* c4 = acc[mt * 8 + nt];
            int row = r0 + mt * 16;
            int col = n0 + wn0 + nt * 8 + c0l;
            float2 bi = *(const float2*)(bias + col);
            float v0 = c4[0] + bi.x, v1 = c4[1] + bi.y;
            float v2 = c4[2] + bi.x, v3 = c4[3] + bi.y;
            if (mode == 0) {
                *(float2*)(C + (size_t)row * N + col) = make_float2(v0, v1);
                *(float2*)(C + (size_t)(row + 8) * N + col) = make_float2(v2, v3);
            } else {
                *(uint32_t*)(Ch + (size_t)row * N + col) = pack2h(v0, v1);
                *(uint32_t*)(Ch + (size_t)(row + 8) * N + col) = pack2h(v2, v3);
            }
        }
}

// ---------------------------------------------------------------------------
// Tensor-core causal flash attention, fp16 operands, fp32 accum/softmax.
// ---------------------------------------------------------------------------
#define AT_STR 72                          // smem stride in fp16 (144 B)
#define Q_TILE_B (128 * AT_STR * 2)        // 18432
#define KV_TILE_B (64 * AT_STR * 2)        // 9216
#define KV_STAGE_B (2 * KV_TILE_B)         // K, V
#define ATT_SMEM (Q_TILE_B + 2 * KV_STAGE_B)  // 55296

__global__ void __launch_bounds__(256, 2) flash_attn_mma(
    const __half* __restrict__ qkv, __half* __restrict__ att)
{
    extern __shared__ char smem[];
    const uint32_t sb = smem_u32(smem);
    const uint32_t QH = 0, ST0 = Q_TILE_B;
    const int t = threadIdx.x, l = t & 31, w = t >> 5;
    const int qt = (int)(gridDim.x - 1 - blockIdx.x);   // heavy tiles first
    const int h = blockIdx.y, b = blockIdx.z;
    const int q0 = qt * 128;
    const size_t tok0 = (size_t)b * SEQ;

#pragma unroll
    for (int it = 0; it < 4; it++) {
        int idx = t + it * 256;             // 0..1023 over [128 r][8 seg]
        int r = idx >> 3, seg = idx & 7;
        size_t src = (tok0 + q0 + r) * N_QKV + h * HEAD_DIM + seg * 8;
        cp_async16(sb + QH + (r * AT_STR + seg * 8) * 2, qkv + src);
    }
    asm volatile("cp.async.commit_group;" ::: "memory");

    auto load_kv = [&](int kt, int s) {
        uint32_t stg = sb + ST0 + s * KV_STAGE_B;
        int k0 = kt * 64;
#pragma unroll
        for (int it = 0; it < 2; it++) {
            int idx = t + it * 256;         // 0..511 over [64 r][8 seg]
            int r = idx >> 3, seg = idx & 7;
            size_t srcK = (tok0 + k0 + r) * N_QKV + D_MODEL + h * HEAD_DIM + seg * 8;
            uint32_t dst = (r * AT_STR + seg * 8) * 2;
            cp_async16(stg + 0 * KV_TILE_B + dst, qkv + srcK);
            cp_async16(stg + 1 * KV_TILE_B + dst, qkv + srcK + D_MODEL);
        }
        asm volatile("cp.async.commit_group;" ::: "memory");
    };

    load_kv(0, 0);
    asm volatile("cp.async.wait_group 1;" ::: "memory");   // Q ready
    __syncthreads();

    uint32_t qfh[4][4];
    const uint32_t a_off = ((w * 16 + (l & 15)) * AT_STR + (l >> 4) * 8) * 2;
#pragma unroll
    for (int ks = 0; ks < 4; ks++)
        ldsm_x4(qfh[ks], sb + QH + a_off + ks * 32);

    float M0 = -1e30f, M1 = -1e30f, L0 = 0.f, L1 = 0.f;
    float o[8][4];
#pragma unroll
    for (int i = 0; i < 8; i++)
#pragma unroll
        for (int j = 0; j < 4; j++) o[i][j] = 0.f;

    const uint32_t kb_off = (((l & 7) + ((l >> 4) << 3)) * AT_STR +
                             ((l >> 3) & 1) * 8) * 2;
    const uint32_t vb_off = ((l & 15) * AT_STR + (l >> 4) * 8) * 2;
    const int row0 = q0 + w * 16 + (l >> 2);
    const int colq = (l & 3) * 2;
    const int NT = 2 * qt + 2;

    for (int kt = 0; kt < NT; kt++) {
        if (kt + 1 < NT) {
            load_kv(kt + 1, (kt + 1) & 1);
            asm volatile("cp.async.wait_group 1;" ::: "memory");
        } else {
            asm volatile("cp.async.wait_group 0;" ::: "memory");
        }
        __syncthreads();
        const uint32_t stg = sb + ST0 + (kt & 1) * KV_STAGE_B;

        float sacc[8][4];
#pragma unroll
        for (int i = 0; i < 8; i++)
#pragma unroll
            for (int j = 0; j < 4; j++) sacc[i][j] = 0.f;

#pragma unroll
        for (int ks = 0; ks < 4; ks++) {
#pragma unroll
            for (int np = 0; np < 4; np++) {
                uint32_t bh[4];
                uint32_t o2 = (np * 16 * AT_STR + ks * 16) * 2;
                ldsm_x4(bh, stg + 0 * KV_TILE_B + kb_off + o2);
                mma16816(sacc[2 * np], qfh[ks], bh);
                mma16816(sacc[2 * np + 1], qfh[ks], bh + 2);
            }
        }

        const int k0 = kt * 64;
        const bool dm = (kt >= 2 * qt);
#pragma unroll
        for (int nt = 0; nt < 8; nt++) {
            int colb = k0 + nt * 8 + colq;
#pragma unroll
            for (int j = 0; j < 4; j++) {
                float v = sacc[nt][j] * 0.125f;
                if (dm && (colb + (j & 1)) > (row0 + (j >> 1) * 8)) v = -1e30f;
                sacc[nt][j] = v;
            }
        }

        float m0 = -1e30f, m1 = -1e30f;
#pragma unroll
        for (int nt = 0; nt < 8; nt++) {
            m0 = fmaxf(m0, fmaxf(sacc[nt][0], sacc[nt][1]));
            m1 = fmaxf(m1, fmaxf(sacc[nt][2], sacc[nt][3]));
        }
        m0 = fmaxf(m0, __shfl_xor_sync(~0u, m0, 1));
        m0 = fmaxf(m0, __shfl_xor_sync(~0u, m0, 2));
        m1 = fmaxf(m1, __shfl_xor_sync(~0u, m1, 1));
        m1 = fmaxf(m1, __shfl_xor_sync(~0u, m1, 2));
        float Mn0 = fmaxf(M0, m0), Mn1 = fmaxf(M1, m1);
        float f0 = __expf(M0 - Mn0), f1 = __expf(M1 - Mn1);
        float rs0 = 0.f, rs1 = 0.f;
#pragma unroll
        for (int nt = 0; nt < 8; nt++) {
            sacc[nt][0] = __expf(sacc[nt][0] - Mn0);
            sacc[nt][1] = __expf(sacc[nt][1] - Mn0);
            sacc[nt][2] = __expf(sacc[nt][2] - Mn1);
            sacc[nt][3] = __expf(sacc[nt][3] - Mn1);
            rs0 += sacc[nt][0] + sacc[nt][1];
            rs1 += sacc[nt][2] + sacc[nt][3];
        }
        rs0 += __shfl_xor_sync(~0u, rs0, 1);
        rs0 += __shfl_xor_sync(~0u, rs0, 2);
        rs1 += __shfl_xor_sync(~0u, rs1, 1);
        rs1 += __shfl_xor_sync(~0u, rs1, 2);
        L0 = L0 * f0 + rs0; L1 = L1 * f1 + rs1;
        M0 = Mn0; M1 = Mn1;

#pragma unroll
        for (int nt = 0; nt < 8; nt++) {
            o[nt][0] *= f0; o[nt][1] *= f0;
            o[nt][2] *= f1; o[nt][3] *= f1;
        }

#pragma unroll
        for (int ks = 0; ks < 4; ks++) {
            uint32_t ph[4];
            ph[0] = pack2h(sacc[2 * ks][0], sacc[2 * ks][1]);
            ph[1] = pack2h(sacc[2 * ks][2], sacc[2 * ks][3]);
            ph[2] = pack2h(sacc[2 * ks + 1][0], sacc[2 * ks + 1][1]);
            ph[3] = pack2h(sacc[2 * ks + 1][2], sacc[2 * ks + 1][3]);
#pragma unroll
            for (int np = 0; np < 4; np++) {
                uint32_t vh[4];
                uint32_t o2 = (ks * 16 * AT_STR + np * 16) * 2;
                ldsm_x4_t(vh, stg + 1 * KV_TILE_B + vb_off + o2);
                mma16816(o[2 * np], ph, vh);
                mma16816(o[2 * np + 1], ph, vh + 2);
            }
        }
        __syncthreads();
    }

    const float i0 = 1.f / L0, i1 = 1.f / L1;
#pragma unroll
    for (int nt = 0; nt < 8; nt++) {
        int col = h * HEAD_DIM + nt * 8 + colq;
        size_t r0 = (tok0 + row0) * D_MODEL + col;
        size_t r1 = (tok0 + row0 + 8) * D_MODEL + col;
        *(uint32_t*)(att + r0) = pack2h(o[nt][0] * i0, o[nt][1] * i0);
        *(uint32_t*)(att + r1) = pack2h(o[nt][2] * i1, o[nt][3] * i1);
    }
}

// ---------------------------------------------------------------------------
extern "C" void kernel_launch(void* const* d_in, const int* in_sizes, int n_in,
                              void* d_out, int out_size)
{
    const float* x     = (const float*)d_in[0];
    const float* qkv_w = (const float*)d_in[1];
    const float* qkv_b = (const float*)d_in[2];
    const float* out_w = (const float*)d_in[3];
    const float* out_b = (const float*)d_in[4];
    float* out = (float*)d_out;

    __half *qkv, *xh, *wq, *wo, *att;
    cudaGetSymbolAddress((void**)&qkv, g_qkv);
    cudaGetSymbolAddress((void**)&xh, g_x);
    cudaGetSymbolAddress((void**)&wq, g_wq);
    cudaGetSymbolAddress((void**)&wo, g_wo);
    cudaGetSymbolAddress((void**)&att, g_att);

    cudaFuncSetAttribute(gemm_mma, cudaFuncAttributeMaxDynamicSharedMemorySize,
                         GEMM_SMEM);
    cudaFuncSetAttribute(flash_attn_mma, cudaFuncAttributeMaxDynamicSharedMemorySize,
                         ATT_SMEM);

    int n2x = M_TOT * D_MODEL / 2;
    int n2q = N_QKV * D_MODEL / 2;
    int n2o = D_MODEL * D_MODEL / 2;
    round_fp16<<<(n2x + 255) / 256, 256>>>((const float2*)x, (__half2*)xh, n2x);
    round_fp16<<<(n2q + 255) / 256, 256>>>((const float2*)qkv_w, (__half2*)wq, n2q);
    round_fp16<<<(n2o + 255) / 256, 256>>>((const float2*)out_w, (__half2*)wo, n2o);

    // 1) QKV projection -> fp16
    gemm_mma<<<dim3(N_QKV / 128, M_TOT / 128), 256, GEMM_SMEM>>>(
        xh, wq, qkv_b, nullptr, qkv, N_QKV, D_MODEL, 2);

    // 2) Tensor-core causal flash attention -> fp16
    flash_attn_mma<<<dim3(SEQ / 128, N_HEADS, BATCH), 256, ATT_SMEM>>>(qkv, att);

    // 3) Output projection -> fp32 final
    gemm_mma<<<dim3(D_MODEL / 128, M_TOT / 128), 256, GEMM_SMEM>>>(
        att, wo, out_b, out, nullptr, D_MODEL, D_MODEL, 0);
}

// round 9
// speedup vs baseline: 7.1551x; 1.0671x over previous
#include <cuda_runtime.h>
#include <cuda_fp16.h>
#include <math.h>
#include <float.h>
#include <cstdint>

#define D_MODEL  1024
#define N_HEADS  16
#define HEAD_DIM 64
#define BATCH    2
#define SEQ      2048
#define M_TOT    (BATCH * SEQ)     // 4096
#define N_QKV    (3 * D_MODEL)     // 3072

// ---------------- scratch (allocation-free rule: __device__ globals) --------
__device__ __half g_qkv[(size_t)M_TOT * N_QKV];
__device__ __half g_x[(size_t)M_TOT * D_MODEL];
__device__ __half g_wq[(size_t)N_QKV * D_MODEL];
__device__ __half g_wo[(size_t)D_MODEL * D_MODEL];
__device__ __half g_att[(size_t)M_TOT * D_MODEL];

// ---------------- helpers ---------------------------------------------------
__device__ __forceinline__ uint32_t smem_u32(const void* p) {
    uint32_t a;
    asm("{ .reg .u64 t; cvta.to.shared.u64 t, %1; cvt.u32.u64 %0, t; }"
        : "=r"(a) : "l"(p));
    return a;
}
__device__ __forceinline__ void cp_async16(uint32_t dst, const void* src) {
    asm volatile("cp.async.cg.shared.global [%0], [%1], 16;" :: "r"(dst), "l"(src)
                 : "memory");
}
__device__ __forceinline__ void ldsm_x4(uint32_t* r, uint32_t addr) {
    asm volatile("ldmatrix.sync.aligned.m8n8.x4.shared.b16 {%0,%1,%2,%3}, [%4];"
        : "=r"(r[0]), "=r"(r[1]), "=r"(r[2]), "=r"(r[3]) : "r"(addr));
}
__device__ __forceinline__ void ldsm_x4_t(uint32_t* r, uint32_t addr) {
    asm volatile("ldmatrix.sync.aligned.m8n8.x4.trans.shared.b16 {%0,%1,%2,%3}, [%4];"
        : "=r"(r[0]), "=r"(r[1]), "=r"(r[2]), "=r"(r[3]) : "r"(addr));
}
__device__ __forceinline__ void mma16816(float* c, const uint32_t* a, const uint32_t* b) {
    asm volatile("mma.sync.aligned.m16n8k16.row.col.f32.f16.f16.f32 "
        "{%0,%1,%2,%3}, {%4,%5,%6,%7}, {%8,%9}, {%0,%1,%2,%3};"
        : "+f"(c[0]), "+f"(c[1]), "+f"(c[2]), "+f"(c[3])
        : "r"(a[0]), "r"(a[1]), "r"(a[2]), "r"(a[3]), "r"(b[0]), "r"(b[1]));
}
__device__ __forceinline__ uint32_t pack2h(float a, float b) {
    __half2 h = __floats2half2_rn(a, b);
    return *(uint32_t*)&h;
}

// ---------------- fused fp32 -> fp16 rounding (x, qkv_w, out_w) -------------
__global__ void __launch_bounds__(256) round_all(
    const float2* __restrict__ x,  __half2* __restrict__ xo,  int nx,
    const float2* __restrict__ w1, __half2* __restrict__ w1o, int n1,
    const float2* __restrict__ w2, __half2* __restrict__ w2o, int n2)
{
    int i = blockIdx.x * blockDim.x + threadIdx.x;
    if (i < nx) {
        float2 v = x[i];
        xo[i] = __floats2half2_rn(v.x, v.y);
    } else if (i < nx + n1) {
        float2 v = w1[i - nx];
        w1o[i - nx] = __floats2half2_rn(v.x, v.y);
    } else if (i < nx + n1 + n2) {
        float2 v = w2[i - nx - n1];
        w2o[i - nx - n1] = __floats2half2_rn(v.x, v.y);
    }
}

// ---------------- mma.sync fp16 GEMM, BK=64, 3-stage ring (unchanged) -------
#define GTILE_B  (128 * 128)
#define GSTAGE_B (2 * GTILE_B)
#define GEMM_SMEM (3 * GSTAGE_B)

__global__ void __launch_bounds__(256, 2) gemm_mma(
    const __half* __restrict__ A, const __half* __restrict__ B,
    const float* __restrict__ bias, float* __restrict__ C,
    __half* __restrict__ Ch, int N, int K, int mode)
{
    extern __shared__ char smem[];
    const uint32_t sbase = smem_u32(smem);
    const int t = threadIdx.x, lane = t & 31, wid = t >> 5;
    const int wm0 = (wid & 3) * 32, wn0 = (wid >> 2) * 64;
    const int m0 = blockIdx.y * 128, n0 = blockIdx.x * 128;

    auto load = [&](int c, int st) {
        uint32_t stg = sbase + st * GSTAGE_B;
#pragma unroll
        for (int i = 0; i < 8; i++) {
            int idx = t + i * 256;
            int tile = idx >> 10;
            int r = (idx >> 3) & 127;
            int s = idx & 7;
            int row0 = tile ? n0 : m0;
            const __half* src = tile ? B : A;
            uint32_t sw = r * 128 + (((s ^ (r & 7)) & 7) << 4);
            cp_async16(stg + tile * GTILE_B + sw,
                       src + (size_t)(row0 + r) * K + c * 64 + s * 8);
        }
        asm volatile("cp.async.commit_group;" ::: "memory");
    };

    float acc[16][4];
#pragma unroll
    for (int i = 0; i < 16; i++)
#pragma unroll
        for (int j = 0; j < 4; j++) acc[i][j] = 0.0f;

    const int l15 = lane & 15;
    const uint32_t arx = l15 & 7;
    uint32_t ar128[2];
    ar128[0] = (wm0 + l15) * 128;
    ar128[1] = (wm0 + 16 + l15) * 128;
    const uint32_t brbase = wn0 + ((lane >> 4) << 3) + (lane & 7);
    const uint32_t brx = brbase & 7;
    const uint32_t bsel = (lane >> 3) & 1;

    const int NC = K / 64;
    load(0, 0);
    load(1, 1);

    for (int c = 0; c < NC; c++) {
        if (c + 1 < NC)
            asm volatile("cp.async.wait_group 1;" ::: "memory");
        else
            asm volatile("cp.async.wait_group 0;" ::: "memory");
        __syncthreads();
        if (c + 2 < NC) {
            int st2 = c + 2;
            st2 -= (st2 / 3) * 3;
            load(c + 2, st2);
        }

        int stidx = c; stidx -= (stidx / 3) * 3;
        const uint32_t stg = sbase + stidx * GSTAGE_B;
#pragma unroll
        for (int kk = 0; kk < 4; kk++) {
            uint32_t af[2][4];
            const uint32_t sA = kk * 2 + (lane >> 4);
#pragma unroll
            for (int mt = 0; mt < 2; mt++) {
                uint32_t col = ((sA ^ arx) & 7) << 4;
                ldsm_x4(af[mt], stg + ar128[mt] + col);
            }
            const uint32_t sB = kk * 2 + bsel;
            const uint32_t bcol = ((sB ^ brx) & 7) << 4;
#pragma unroll
            for (int nt2 = 0; nt2 < 4; nt2++) {
                uint32_t bh[4];
                uint32_t baddr = (brbase + nt2 * 16) * 128 + bcol;
                ldsm_x4(bh, stg + GTILE_B + baddr);
#pragma unroll
                for (int mt = 0; mt < 2; mt++) {
                    mma16816(acc[mt * 8 + nt2 * 2], af[mt], bh);
                    mma16816(acc[mt * 8 + nt2 * 2 + 1], af[mt], bh + 2);
                }
            }
        }
    }

    const int r0 = m0 + wm0 + (lane >> 2);
    const int c0l = (lane & 3) * 2;
#pragma unroll
    for (int mt = 0; mt < 2; mt++)
#pragma unroll
        for (int nt = 0; nt < 8; nt++) {
            const float* c4 = acc[mt * 8 + nt];
            int row = r0 + mt * 16;
            int col = n0 + wn0 + nt * 8 + c0l;
            float2 bi = *(const float2*)(bias + col);
            float v0 = c4[0] + bi.x, v1 = c4[1] + bi.y;
            float v2 = c4[2] + bi.x, v3 = c4[3] + bi.y;
            if (mode == 0) {
                *(float2*)(C + (size_t)row * N + col) = make_float2(v0, v1);
                *(float2*)(C + (size_t)(row + 8) * N + col) = make_float2(v2, v3);
            } else {
                *(uint32_t*)(Ch + (size_t)row * N + col) = pack2h(v0, v1);
                *(uint32_t*)(Ch + (size_t)(row + 8) * N + col) = pack2h(v2, v3);
            }
        }
}

// ---------------------------------------------------------------------------
// Split-KV-column causal flash attention.
// 128 thr (4 warps, 2x2). Q tile 64. Warp = 32 Q-rows x 32 KV-cols with
// independent online softmax (M,L,O), merged once at the end via smem.
// ---------------------------------------------------------------------------
#define AQ_STR 72                          // smem stride in fp16 (144 B)
#define AQ_TILE_B (64 * AQ_STR * 2)        // 9216 (Q)
#define AKV_TILE_B (64 * AQ_STR * 2)       // 9216
#define AKV_STAGE_B (2 * AKV_TILE_B)       // K + V
#define ATT_SMEM (AQ_TILE_B + 3 * AKV_STAGE_B)  // 64512

__global__ void __launch_bounds__(128, 3) flash_attn_mma(
    const __half* __restrict__ qkv, __half* __restrict__ att)
{
    extern __shared__ char smem[];
    const uint32_t sb = smem_u32(smem);
    const uint32_t ST0 = AQ_TILE_B;
    const int t = threadIdx.x, l = t & 31, w = t >> 5;
    const int wr = w >> 1, wc = w & 1;
    const int qt = (int)(gridDim.x - 1 - blockIdx.x);   // heavy tiles first
    const int h = blockIdx.y, b = blockIdx.z;
    const int q0 = qt * 64;
    const size_t tok0 = (size_t)b * SEQ;
    const int NT = qt + 1;

    // Q tile load (group 0)
#pragma unroll
    for (int it = 0; it < 4; it++) {
        int idx = t + it * 128;             // 0..511 over [64 r][8 seg]
        int r = idx >> 3, seg = idx & 7;
        size_t src = (tok0 + q0 + r) * N_QKV + h * HEAD_DIM + seg * 8;
        cp_async16(sb + (r * AQ_STR + seg * 8) * 2, qkv + src);
    }
    asm volatile("cp.async.commit_group;" ::: "memory");

    auto load_kv = [&](int kt, int s) {
        uint32_t stg = sb + ST0 + s * AKV_STAGE_B;
        int k0 = kt * 64;
#pragma unroll
        for (int it = 0; it < 4; it++) {
            int idx = t + it * 128;
            int r = idx >> 3, seg = idx & 7;
            size_t srcK = (tok0 + k0 + r) * N_QKV + D_MODEL + h * HEAD_DIM + seg * 8;
            uint32_t dst = (r * AQ_STR + seg * 8) * 2;
            cp_async16(stg + dst, qkv + srcK);
            cp_async16(stg + AKV_TILE_B + dst, qkv + srcK + D_MODEL);
        }
        asm volatile("cp.async.commit_group;" ::: "memory");
    };

    load_kv(0, 0);
    if (NT > 1) {
        load_kv(1, 1);
        asm volatile("cp.async.wait_group 2;" ::: "memory");  // Q done
    } else {
        asm volatile("cp.async.wait_group 1;" ::: "memory");
    }
    __syncthreads();

    // Hoist Q A-fragments: rows 32*wr .. +31, all 4 k16 steps
    uint32_t qf[2][4][4];
#pragma unroll
    for (int mt = 0; mt < 2; mt++)
#pragma unroll
        for (int ks = 0; ks < 4; ks++)
            ldsm_x4(qf[mt][ks],
                sb + ((32 * wr + 16 * mt + (l & 15)) * AQ_STR +
                      (l >> 4) * 8 + ks * 16) * 2);

    float M[4], L[4], o[2][8][4];
#pragma unroll
    for (int i = 0; i < 4; i++) { M[i] = -1e30f; L[i] = 0.f; }
#pragma unroll
    for (int mt = 0; mt < 2; mt++)
#pragma unroll
        for (int nt = 0; nt < 8; nt++)
#pragma unroll
            for (int j = 0; j < 4; j++) o[mt][nt][j] = 0.f;

    const int rowq = q0 + 32 * wr + (l >> 2);   // + mt*16 + half*8
    const int colw = 32 * wc + (l & 3) * 2;     // + nt*8 (within KV tile)
    const float SC2 = 0.18033688011f;           // 0.125 * log2(e)

    for (int kt = 0; kt < NT; kt++) {
        if (kt + 1 < NT)
            asm volatile("cp.async.wait_group 1;" ::: "memory");
        else
            asm volatile("cp.async.wait_group 0;" ::: "memory");
        __syncthreads();
        if (kt + 2 < NT) {
            int s2 = kt + 2; s2 -= (s2 / 3) * 3;
            load_kv(kt + 2, s2);
        }
        int si = kt; si -= (si / 3) * 3;
        const uint32_t stg = sb + ST0 + si * AKV_STAGE_B;

        // S = Q K^T for 32x32 warp block
        float sacc[2][4][4];
#pragma unroll
        for (int mt = 0; mt < 2; mt++)
#pragma unroll
            for (int nt = 0; nt < 4; nt++)
#pragma unroll
                for (int j = 0; j < 4; j++) sacc[mt][nt][j] = 0.f;

#pragma unroll
        for (int ks = 0; ks < 4; ks++) {
#pragma unroll
            for (int np = 0; np < 2; np++) {
                uint32_t bh[4];
                ldsm_x4(bh, stg +
                    ((32 * wc + np * 16 + ((l >> 4) << 3) + (l & 7)) * AQ_STR +
                     ((l >> 3) & 1) * 8 + ks * 16) * 2);
#pragma unroll
                for (int mt = 0; mt < 2; mt++) {
                    mma16816(sacc[mt][2 * np], qf[mt][ks], bh);
                    mma16816(sacc[mt][2 * np + 1], qf[mt][ks], bh + 2);
                }
            }
        }

        // scale (log2 domain) + causal mask (only diagonal tile kt==qt)
        const int k0 = kt * 64;
        const bool dm = (kt == qt);
#pragma unroll
        for (int mt = 0; mt < 2; mt++)
#pragma unroll
            for (int nt = 0; nt < 4; nt++)
#pragma unroll
                for (int j = 0; j < 4; j++) {
                    float v = sacc[mt][nt][j] * SC2;
                    if (dm && (k0 + colw + nt * 8 + (j & 1)) >
                              (rowq + mt * 16 + (j >> 1) * 8)) v = -1e30f;
                    sacc[mt][nt][j] = v;
                }

        // per-warp online softmax (independent per KV-col group)
#pragma unroll
        for (int mt = 0; mt < 2; mt++)
#pragma unroll
            for (int half = 0; half < 2; half++) {
                const int mi = mt * 2 + half;
                const int jb = half * 2;
                float mloc = -1e30f;
#pragma unroll
                for (int nt = 0; nt < 4; nt++)
                    mloc = fmaxf(mloc, fmaxf(sacc[mt][nt][jb], sacc[mt][nt][jb + 1]));
                mloc = fmaxf(mloc, __shfl_xor_sync(~0u, mloc, 1));
                mloc = fmaxf(mloc, __shfl_xor_sync(~0u, mloc, 2));
                float Mn = fmaxf(M[mi], mloc);
                float f = exp2f(M[mi] - Mn);
                float rs = 0.f;
#pragma unroll
                for (int nt = 0; nt < 4; nt++) {
                    float p0 = exp2f(sacc[mt][nt][jb] - Mn);
                    float p1 = exp2f(sacc[mt][nt][jb + 1] - Mn);
                    sacc[mt][nt][jb] = p0; sacc[mt][nt][jb + 1] = p1;
                    rs += p0 + p1;
                }
                rs += __shfl_xor_sync(~0u, rs, 1);
                rs += __shfl_xor_sync(~0u, rs, 2);
                L[mi] = L[mi] * f + rs;
                M[mi] = Mn;
#pragma unroll
                for (int nt = 0; nt < 8; nt++) {
                    o[mt][nt][jb] *= f;
                    o[mt][nt][jb + 1] *= f;
                }
            }

        // O += P V  (P = warp's 32x32 probs, V rows = warp's 32 KV rows)
#pragma unroll
        for (int kp = 0; kp < 2; kp++) {
            uint32_t ph[2][4];
#pragma unroll
            for (int mt = 0; mt < 2; mt++) {
                ph[mt][0] = pack2h(sacc[mt][2 * kp][0], sacc[mt][2 * kp][1]);
                ph[mt][1] = pack2h(sacc[mt][2 * kp][2], sacc[mt][2 * kp][3]);
                ph[mt][2] = pack2h(sacc[mt][2 * kp + 1][0], sacc[mt][2 * kp + 1][1]);
                ph[mt][3] = pack2h(sacc[mt][2 * kp + 1][2], sacc[mt][2 * kp + 1][3]);
            }
#pragma unroll
            for (int np = 0; np < 4; np++) {
                uint32_t vh[4];
                ldsm_x4_t(vh, stg + AKV_TILE_B +
                    ((32 * wc + kp * 16 + (l & 15)) * AQ_STR +
                     np * 16 + (l >> 4) * 8) * 2);
#pragma unroll
                for (int mt = 0; mt < 2; mt++) {
                    mma16816(o[mt][2 * np], ph[mt], vh);
                    mma16816(o[mt][2 * np + 1], ph[mt], vh + 2);
                }
            }
        }
    }

    // ---- merge the two KV-col groups (wc=1 -> smem -> wc=0 combines) ----
    __syncthreads();
    const int OSTR = 65;                       // conflict-free lane stride
    const uint32_t mb = sb + wr * (32 * OSTR * 4 + 1024);
    if (wc == 1) {
#pragma unroll
        for (int mt = 0; mt < 2; mt++)
#pragma unroll
            for (int nt = 0; nt < 8; nt++)
#pragma unroll
                for (int j = 0; j < 4; j++) {
                    int idx = mt * 32 + nt * 4 + j;
                    *(float*)(smem + (mb - sb) + (l * OSTR + idx) * 4) = o[mt][nt][j];
                }
#pragma unroll
        for (int i = 0; i < 4; i++) {
            *(float*)(smem + (mb - sb) + 32 * OSTR * 4 + l * 32 + i * 4) = M[i];
            *(float*)(smem + (mb - sb) + 32 * OSTR * 4 + l * 32 + 16 + i * 4) = L[i];
        }
    }
    __syncthreads();
    if (wc == 0) {
        float w0s[4], w1s[4], inv[4];
#pragma unroll
        for (int i = 0; i < 4; i++) {
            float M1 = *(float*)(smem + (mb - sb) + 32 * OSTR * 4 + l * 32 + i * 4);
            float L1 = *(float*)(smem + (mb - sb) + 32 * OSTR * 4 + l * 32 + 16 + i * 4);
            float Mx = fmaxf(M[i], M1);
            w0s[i] = exp2f(M[i] - Mx);
            w1s[i] = exp2f(M1 - Mx);
            inv[i] = 1.f / (L[i] * w0s[i] + L1 * w1s[i]);
        }
#pragma unroll
        for (int mt = 0; mt < 2; mt++)
#pragma unroll
            for (int nt = 0; nt < 8; nt++) {
                float v[4];
#pragma unroll
                for (int j = 0; j < 4; j++) {
                    int idx = mt * 32 + nt * 4 + j;
                    float o1 = *(float*)(smem + (mb - sb) + (l * OSTR + idx) * 4);
                    int mi = mt * 2 + (j >> 1);
                    v[j] = (o[mt][nt][j] * w0s[mi] + o1 * w1s[mi]) * inv[mi];
                }
                int col = h * HEAD_DIM + nt * 8 + (l & 3) * 2;
                size_t r0 = (tok0 + q0 + 32 * wr + mt * 16 + (l >> 2)) * D_MODEL + col;
                *(uint32_t*)(att + r0) = pack2h(v[0], v[1]);
                *(uint32_t*)(att + r0 + 8 * D_MODEL) = pack2h(v[2], v[3]);
            }
    }
}

// ---------------------------------------------------------------------------
extern "C" void kernel_launch(void* const* d_in, const int* in_sizes, int n_in,
                              void* d_out, int out_size)
{
    const float* x     = (const float*)d_in[0];
    const float* qkv_w = (const float*)d_in[1];
    const float* qkv_b = (const float*)d_in[2];
    const float* out_w = (const float*)d_in[3];
    const float* out_b = (const float*)d_in[4];
    float* out = (float*)d_out;

    __half *qkv, *xh, *wq, *wo, *att;
    cudaGetSymbolAddress((void**)&qkv, g_qkv);
    cudaGetSymbolAddress((void**)&xh, g_x);
    cudaGetSymbolAddress((void**)&wq, g_wq);
    cudaGetSymbolAddress((void**)&wo, g_wo);
    cudaGetSymbolAddress((void**)&att, g_att);

    cudaFuncSetAttribute(gemm_mma, cudaFuncAttributeMaxDynamicSharedMemorySize,
                         GEMM_SMEM);
    cudaFuncSetAttribute(flash_attn_mma, cudaFuncAttributeMaxDynamicSharedMemorySize,
                         ATT_SMEM);

    int n2x = M_TOT * D_MODEL / 2;
    int n2q = N_QKV * D_MODEL / 2;
    int n2o = D_MODEL * D_MODEL / 2;
    int n2tot = n2x + n2q + n2o;
    round_all<<<(n2tot + 255) / 256, 256>>>(
        (const float2*)x, (__half2*)xh, n2x,
        (const float2*)qkv_w, (__half2*)wq, n2q,
        (const float2*)out_w, (__half2*)wo, n2o);

    // 1) QKV projection -> fp16
    gemm_mma<<<dim3(N_QKV / 128, M_TOT / 128), 256, GEMM_SMEM>>>(
        xh, wq, qkv_b, nullptr, qkv, N_QKV, D_MODEL, 2);

    // 2) Split-KV-column causal flash attention -> fp16
    flash_attn_mma<<<dim3(SEQ / 64, N_HEADS, BATCH), 128, ATT_SMEM>>>(qkv, att);

    // 3) Output projection -> fp32 final
    gemm_mma<<<dim3(D_MODEL / 128, M_TOT / 128), 256, GEMM_SMEM>>>(
        att, wo, out_b, out, nullptr, D_MODEL, D_MODEL, 0);
}

// round 10
// speedup vs baseline: 7.8172x; 1.0925x over previous
#include <cuda_runtime.h>
#include <cuda_fp16.h>
#include <math.h>
#include <float.h>
#include <cstdint>

#define D_MODEL  1024
#define N_HEADS  16
#define HEAD_DIM 64
#define BATCH    2
#define SEQ      2048
#define M_TOT    (BATCH * SEQ)     // 4096
#define N_QKV    (3 * D_MODEL)     // 3072

// ---------------- scratch (allocation-free rule: __device__ globals) --------
__device__ __half g_qkv[(size_t)M_TOT * N_QKV];
__device__ __half g_x[(size_t)M_TOT * D_MODEL];
__device__ __half g_wq[(size_t)N_QKV * D_MODEL];
__device__ __half g_wo[(size_t)D_MODEL * D_MODEL];
__device__ __half g_att[(size_t)M_TOT * D_MODEL];

// ---------------- helpers ---------------------------------------------------
__device__ __forceinline__ uint32_t smem_u32(const void* p) {
    uint32_t a;
    asm("{ .reg .u64 t; cvta.to.shared.u64 t, %1; cvt.u32.u64 %0, t; }"
        : "=r"(a) : "l"(p));
    return a;
}
__device__ __forceinline__ void cp_async16(uint32_t dst, const void* src) {
    asm volatile("cp.async.cg.shared.global [%0], [%1], 16;" :: "r"(dst), "l"(src)
                 : "memory");
}
__device__ __forceinline__ void ldsm_x4(uint32_t* r, uint32_t addr) {
    asm volatile("ldmatrix.sync.aligned.m8n8.x4.shared.b16 {%0,%1,%2,%3}, [%4];"
        : "=r"(r[0]), "=r"(r[1]), "=r"(r[2]), "=r"(r[3]) : "r"(addr));
}
__device__ __forceinline__ void ldsm_x4_t(uint32_t* r, uint32_t addr) {
    asm volatile("ldmatrix.sync.aligned.m8n8.x4.trans.shared.b16 {%0,%1,%2,%3}, [%4];"
        : "=r"(r[0]), "=r"(r[1]), "=r"(r[2]), "=r"(r[3]) : "r"(addr));
}
__device__ __forceinline__ void mma16816(float* c, const uint32_t* a, const uint32_t* b) {
    asm volatile("mma.sync.aligned.m16n8k16.row.col.f32.f16.f16.f32 "
        "{%0,%1,%2,%3}, {%4,%5,%6,%7}, {%8,%9}, {%0,%1,%2,%3};"
        : "+f"(c[0]), "+f"(c[1]), "+f"(c[2]), "+f"(c[3])
        : "r"(a[0]), "r"(a[1]), "r"(a[2]), "r"(a[3]), "r"(b[0]), "r"(b[1]));
}
__device__ __forceinline__ uint32_t pack2h(float a, float b) {
    __half2 h = __floats2half2_rn(a, b);
    return *(uint32_t*)&h;
}

#define SC2F 0.18033688011112042f   // 0.125 * log2(e)

// ---------------- fused fp32 -> fp16 rounding (x, qkv_w, out_w) -------------
__global__ void __launch_bounds__(256) round_all(
    const float2* __restrict__ x,  __half2* __restrict__ xo,  int nx,
    const float2* __restrict__ w1, __half2* __restrict__ w1o, int n1,
    const float2* __restrict__ w2, __half2* __restrict__ w2o, int n2)
{
    int i = blockIdx.x * blockDim.x + threadIdx.x;
    if (i < nx) {
        float2 v = x[i];
        xo[i] = __floats2half2_rn(v.x, v.y);
    } else if (i < nx + n1) {
        float2 v = w1[i - nx];
        w1o[i - nx] = __floats2half2_rn(v.x, v.y);
    } else if (i < nx + n1 + n2) {
        float2 v = w2[i - nx - n1];
        w2o[i - nx - n1] = __floats2half2_rn(v.x, v.y);
    }
}

// ---------------- mma.sync fp16 GEMM: 4 warps, 64x64 warp tile --------------
// C[m,n] = sum_k A[m,k]*B[n,k] + bias[n].  A,B K-major fp16, BK=64, 3-stage.
// mode: 0 = fp32 C;  2 = fp16 Ch, with cols < D_MODEL prescaled by SC2F (Q).
#define GTILE_B  (128 * 128)
#define GSTAGE_B (2 * GTILE_B)
#define GEMM_SMEM (3 * GSTAGE_B)

__global__ void __launch_bounds__(128, 2) gemm_mma(
    const __half* __restrict__ A, const __half* __restrict__ B,
    const float* __restrict__ bias, float* __restrict__ C,
    __half* __restrict__ Ch, int N, int K, int mode)
{
    extern __shared__ char smem[];
    const uint32_t sbase = smem_u32(smem);
    const int t = threadIdx.x, lane = t & 31, wid = t >> 5;
    const int wm0 = (wid & 1) * 64, wn0 = (wid >> 1) * 64;
    const int m0 = blockIdx.y * 128, n0 = blockIdx.x * 128;

    auto load = [&](int c, int st) {
        uint32_t stg = sbase + st * GSTAGE_B;
#pragma unroll
        for (int i = 0; i < 16; i++) {
            int idx = t + i * 128;            // 0..2047: [tile 2][row 128][seg 8]
            int tile = idx >> 10;
            int r = (idx >> 3) & 127;
            int s = idx & 7;
            int row0 = tile ? n0 : m0;
            const __half* src = tile ? B : A;
            uint32_t sw = r * 128 + (((s ^ (r & 7)) & 7) << 4);
            cp_async16(stg + tile * GTILE_B + sw,
                       src + (size_t)(row0 + r) * K + c * 64 + s * 8);
        }
        asm volatile("cp.async.commit_group;" ::: "memory");
    };

    float acc[32][4];
#pragma unroll
    for (int i = 0; i < 32; i++)
#pragma unroll
        for (int j = 0; j < 4; j++) acc[i][j] = 0.0f;

    const int l15 = lane & 15;
    const uint32_t arx = l15 & 7;
    uint32_t ar128[4];
#pragma unroll
    for (int mt = 0; mt < 4; mt++) ar128[mt] = (wm0 + 16 * mt + l15) * 128;
    const uint32_t brbase = wn0 + ((lane >> 4) << 3) + (lane & 7);
    const uint32_t brx = brbase & 7;
    const uint32_t bsel = (lane >> 3) & 1;

    const int NC = K / 64;
    load(0, 0);
    load(1, 1);

    for (int c = 0; c < NC; c++) {
        if (c + 1 < NC)
            asm volatile("cp.async.wait_group 1;" ::: "memory");
        else
            asm volatile("cp.async.wait_group 0;" ::: "memory");
        __syncthreads();
        if (c + 2 < NC) {
            int st2 = c + 2; st2 -= (st2 / 3) * 3;
            load(c + 2, st2);
        }

        int stidx = c; stidx -= (stidx / 3) * 3;
        const uint32_t stg = sbase + stidx * GSTAGE_B;
#pragma unroll
        for (int kk = 0; kk < 4; kk++) {
            uint32_t af[4][4];
            const uint32_t sA = kk * 2 + (lane >> 4);
            const uint32_t colA = ((sA ^ arx) & 7) << 4;
#pragma unroll
            for (int mt = 0; mt < 4; mt++)
                ldsm_x4(af[mt], stg + ar128[mt] + colA);
            const uint32_t sB = kk * 2 + bsel;
            const uint32_t bcol = ((sB ^ brx) & 7) << 4;
#pragma unroll
            for (int nt2 = 0; nt2 < 4; nt2++) {
                uint32_t bh[4];
                ldsm_x4(bh, stg + GTILE_B + (brbase + nt2 * 16) * 128 + bcol);
#pragma unroll
                for (int mt = 0; mt < 4; mt++) {
                    mma16816(acc[mt * 8 + nt2 * 2], af[mt], bh);
                    mma16816(acc[mt * 8 + nt2 * 2 + 1], af[mt], bh + 2);
                }
            }
        }
    }

    const int r0 = m0 + wm0 + (lane >> 2);
    const int c0l = (lane & 3) * 2;
#pragma unroll
    for (int mt = 0; mt < 4; mt++)
#pragma unroll
        for (int nt = 0; nt < 8; nt++) {
            const float* c4 = acc[mt * 8 + nt];
            int row = r0 + mt * 16;
            int col = n0 + wn0 + nt * 8 + c0l;
            float2 bi = *(const float2*)(bias + col);
            float v0 = c4[0] + bi.x, v1 = c4[1] + bi.y;
            float v2 = c4[2] + bi.x, v3 = c4[3] + bi.y;
            if (mode == 0) {
                *(float2*)(C + (size_t)row * N + col) = make_float2(v0, v1);
                *(float2*)(C + (size_t)(row + 8) * N + col) = make_float2(v2, v3);
            } else {
                if (col < D_MODEL) {   // Q columns: fold softmax scale (log2 dom)
                    v0 *= SC2F; v1 *= SC2F; v2 *= SC2F; v3 *= SC2F;
                }
                *(uint32_t*)(Ch + (size_t)row * N + col) = pack2h(v0, v1);
                *(uint32_t*)(Ch + (size_t)(row + 8) * N + col) = pack2h(v2, v3);
            }
        }
}

// ---------------------------------------------------------------------------
// Split-KV-column causal flash attention (Q pre-scaled; exp2 softmax).
// 128 thr (4 warps, 2x2). Q tile 64. Warp = 32 Q-rows x 32 KV-cols.
// ---------------------------------------------------------------------------
#define AQ_STR 72
#define AQ_TILE_B (64 * AQ_STR * 2)
#define AKV_TILE_B (64 * AQ_STR * 2)
#define AKV_STAGE_B (2 * AKV_TILE_B)
#define ATT_SMEM (AQ_TILE_B + 3 * AKV_STAGE_B)  // 64512

__global__ void __launch_bounds__(128, 3) flash_attn_mma(
    const __half* __restrict__ qkv, __half* __restrict__ att)
{
    extern __shared__ char smem[];
    const uint32_t sb = smem_u32(smem);
    const uint32_t ST0 = AQ_TILE_B;
    const int t = threadIdx.x, l = t & 31, w = t >> 5;
    const int wr = w >> 1, wc = w & 1;
    const int qt = (int)(gridDim.x - 1 - blockIdx.x);   // heavy tiles first
    const int h = blockIdx.y, b = blockIdx.z;
    const int q0 = qt * 64;
    const size_t tok0 = (size_t)b * SEQ;
    const int NT = qt + 1;

#pragma unroll
    for (int it = 0; it < 4; it++) {
        int idx = t + it * 128;
        int r = idx >> 3, seg = idx & 7;
        size_t src = (tok0 + q0 + r) * N_QKV + h * HEAD_DIM + seg * 8;
        cp_async16(sb + (r * AQ_STR + seg * 8) * 2, qkv + src);
    }
    asm volatile("cp.async.commit_group;" ::: "memory");

    auto load_kv = [&](int kt, int s) {
        uint32_t stg = sb + ST0 + s * AKV_STAGE_B;
        int k0 = kt * 64;
#pragma unroll
        for (int it = 0; it < 4; it++) {
            int idx = t + it * 128;
            int r = idx >> 3, seg = idx & 7;
            size_t srcK = (tok0 + k0 + r) * N_QKV + D_MODEL + h * HEAD_DIM + seg * 8;
            uint32_t dst = (r * AQ_STR + seg * 8) * 2;
            cp_async16(stg + dst, qkv + srcK);
            cp_async16(stg + AKV_TILE_B + dst, qkv + srcK + D_MODEL);
        }
        asm volatile("cp.async.commit_group;" ::: "memory");
    };

    load_kv(0, 0);
    if (NT > 1) {
        load_kv(1, 1);
        asm volatile("cp.async.wait_group 2;" ::: "memory");  // Q done
    } else {
        asm volatile("cp.async.wait_group 1;" ::: "memory");
    }
    __syncthreads();

    uint32_t qf[2][4][4];
#pragma unroll
    for (int mt = 0; mt < 2; mt++)
#pragma unroll
        for (int ks = 0; ks < 4; ks++)
            ldsm_x4(qf[mt][ks],
                sb + ((32 * wr + 16 * mt + (l & 15)) * AQ_STR +
                      (l >> 4) * 8 + ks * 16) * 2);

    float M[4], L[4], o[2][8][4];
#pragma unroll
    for (int i = 0; i < 4; i++) { M[i] = -1e30f; L[i] = 0.f; }
#pragma unroll
    for (int mt = 0; mt < 2; mt++)
#pragma unroll
        for (int nt = 0; nt < 8; nt++)
#pragma unroll
            for (int j = 0; j < 4; j++) o[mt][nt][j] = 0.f;

    const int rowq = q0 + 32 * wr + (l >> 2);
    const int colw = 32 * wc + (l & 3) * 2;

    for (int kt = 0; kt < NT; kt++) {
        if (kt + 1 < NT)
            asm volatile("cp.async.wait_group 1;" ::: "memory");
        else
            asm volatile("cp.async.wait_group 0;" ::: "memory");
        __syncthreads();
        if (kt + 2 < NT) {
            int s2 = kt + 2; s2 -= (s2 / 3) * 3;
            load_kv(kt + 2, s2);
        }
        int si = kt; si -= (si / 3) * 3;
        const uint32_t stg = sb + ST0 + si * AKV_STAGE_B;

        float sacc[2][4][4];
#pragma unroll
        for (int mt = 0; mt < 2; mt++)
#pragma unroll
            for (int nt = 0; nt < 4; nt++)
#pragma unroll
                for (int j = 0; j < 4; j++) sacc[mt][nt][j] = 0.f;

#pragma unroll
        for (int ks = 0; ks < 4; ks++) {
#pragma unroll
            for (int np = 0; np < 2; np++) {
                uint32_t bh[4];
                ldsm_x4(bh, stg +
                    ((32 * wc + np * 16 + ((l >> 4) << 3) + (l & 7)) * AQ_STR +
                     ((l >> 3) & 1) * 8 + ks * 16) * 2);
#pragma unroll
                for (int mt = 0; mt < 2; mt++) {
                    mma16816(sacc[mt][2 * np], qf[mt][ks], bh);
                    mma16816(sacc[mt][2 * np + 1], qf[mt][ks], bh + 2);
                }
            }
        }

        // causal mask only (S already in log2 domain via pre-scaled Q)
        const int k0 = kt * 64;
        if (kt == qt) {
#pragma unroll
            for (int mt = 0; mt < 2; mt++)
#pragma unroll
                for (int nt = 0; nt < 4; nt++)
#pragma unroll
                    for (int j = 0; j < 4; j++)
                        if ((k0 + colw + nt * 8 + (j & 1)) >
                            (rowq + mt * 16 + (j >> 1) * 8))
                            sacc[mt][nt][j] = -1e30f;
        }

#pragma unroll
        for (int mt = 0; mt < 2; mt++)
#pragma unroll
            for (int half = 0; half < 2; half++) {
                const int mi = mt * 2 + half;
                const int jb = half * 2;
                float mloc = -1e30f;
#pragma unroll
                for (int nt = 0; nt < 4; nt++)
                    mloc = fmaxf(mloc, fmaxf(sacc[mt][nt][jb], sacc[mt][nt][jb + 1]));
                mloc = fmaxf(mloc, __shfl_xor_sync(~0u, mloc, 1));
                mloc = fmaxf(mloc, __shfl_xor_sync(~0u, mloc, 2));
                float Mn = fmaxf(M[mi], mloc);
                float f = exp2f(M[mi] - Mn);
                float rs = 0.f;
#pragma unroll
                for (int nt = 0; nt < 4; nt++) {
                    float p0 = exp2f(sacc[mt][nt][jb] - Mn);
                    float p1 = exp2f(sacc[mt][nt][jb + 1] - Mn);
                    sacc[mt][nt][jb] = p0; sacc[mt][nt][jb + 1] = p1;
                    rs += p0 + p1;
                }
                rs += __shfl_xor_sync(~0u, rs, 1);
                rs += __shfl_xor_sync(~0u, rs, 2);
                L[mi] = L[mi] * f + rs;
                M[mi] = Mn;
#pragma unroll
                for (int nt = 0; nt < 8; nt++) {
                    o[mt][nt][jb] *= f;
                    o[mt][nt][jb + 1] *= f;
                }
            }

#pragma unroll
        for (int kp = 0; kp < 2; kp++) {
            uint32_t ph[2][4];
#pragma unroll
            for (int mt = 0; mt < 2; mt++) {
                ph[mt][0] = pack2h(sacc[mt][2 * kp][0], sacc[mt][2 * kp][1]);
                ph[mt][1] = pack2h(sacc[mt][2 * kp][2], sacc[mt][2 * kp][3]);
                ph[mt][2] = pack2h(sacc[mt][2 * kp + 1][0], sacc[mt][2 * kp + 1][1]);
                ph[mt][3] = pack2h(sacc[mt][2 * kp + 1][2], sacc[mt][2 * kp + 1][3]);
            }
#pragma unroll
            for (int np = 0; np < 4; np++) {
                uint32_t vh[4];
                ldsm_x4_t(vh, stg + AKV_TILE_B +
                    ((32 * wc + kp * 16 + (l & 15)) * AQ_STR +
                     np * 16 + (l >> 4) * 8) * 2);
#pragma unroll
                for (int mt = 0; mt < 2; mt++) {
                    mma16816(o[mt][2 * np], ph[mt], vh);
                    mma16816(o[mt][2 * np + 1], ph[mt], vh + 2);
                }
            }
        }
    }

    // ---- merge the two KV-col groups ----
    __syncthreads();
    const int OSTR = 65;
    const uint32_t mboff = wr * (32 * OSTR * 4 + 1024);
    if (wc == 1) {
#pragma unroll
        for (int mt = 0; mt < 2; mt++)
#pragma unroll
            for (int nt = 0; nt < 8; nt++)
#pragma unroll
                for (int j = 0; j < 4; j++) {
                    int idx = mt * 32 + nt * 4 + j;
                    *(float*)(smem + mboff + (l * OSTR + idx) * 4) = o[mt][nt][j];
                }
#pragma unroll
        for (int i = 0; i < 4; i++) {
            *(float*)(smem + mboff + 32 * OSTR * 4 + l * 32 + i * 4) = M[i];
            *(float*)(smem + mboff + 32 * OSTR * 4 + l * 32 + 16 + i * 4) = L[i];
        }
    }
    __syncthreads();
    if (wc == 0) {
        float w0s[4], w1s[4], inv[4];
#pragma unroll
        for (int i = 0; i < 4; i++) {
            float M1 = *(float*)(smem + mboff + 32 * OSTR * 4 + l * 32 + i * 4);
            float L1 = *(float*)(smem + mboff + 32 * OSTR * 4 + l * 32 + 16 + i * 4);
            float Mx = fmaxf(M[i], M1);
            w0s[i] = exp2f(M[i] - Mx);
            w1s[i] = exp2f(M1 - Mx);
            inv[i] = 1.f / (L[i] * w0s[i] + L1 * w1s[i]);
        }
#pragma unroll
        for (int mt = 0; mt < 2; mt++)
#pragma unroll
            for (int nt = 0; nt < 8; nt++) {
                float v[4];
#pragma unroll
                for (int j = 0; j < 4; j++) {
                    int idx = mt * 32 + nt * 4 + j;
                    float o1 = *(float*)(smem + mboff + (l * OSTR + idx) * 4);
                    int mi = mt * 2 + (j >> 1);
                    v[j] = (o[mt][nt][j] * w0s[mi] + o1 * w1s[mi]) * inv[mi];
                }
                int col = h * HEAD_DIM + nt * 8 + (l & 3) * 2;
                size_t r0 = (tok0 + q0 + 32 * wr + mt * 16 + (l >> 2)) * D_MODEL + col;
                *(uint32_t*)(att + r0) = pack2h(v[0], v[1]);
                *(uint32_t*)(att + r0 + 8 * D_MODEL) = pack2h(v[2], v[3]);
            }
    }
}

// ---------------------------------------------------------------------------
extern "C" void kernel_launch(void* const* d_in, const int* in_sizes, int n_in,
                              void* d_out, int out_size)
{
    const float* x     = (const float*)d_in[0];
    const float* qkv_w = (const float*)d_in[1];
    const float* qkv_b = (const float*)d_in[2];
    const float* out_w = (const float*)d_in[3];
    const float* out_b = (const float*)d_in[4];
    float* out = (float*)d_out;

    __half *qkv, *xh, *wq, *wo, *att;
    cudaGetSymbolAddress((void**)&qkv, g_qkv);
    cudaGetSymbolAddress((void**)&xh, g_x);
    cudaGetSymbolAddress((void**)&wq, g_wq);
    cudaGetSymbolAddress((void**)&wo, g_wo);
    cudaGetSymbolAddress((void**)&att, g_att);

    cudaFuncSetAttribute(gemm_mma, cudaFuncAttributeMaxDynamicSharedMemorySize,
                         GEMM_SMEM);
    cudaFuncSetAttribute(flash_attn_mma, cudaFuncAttributeMaxDynamicSharedMemorySize,
                         ATT_SMEM);

    int n2x = M_TOT * D_MODEL / 2;
    int n2q = N_QKV * D_MODEL / 2;
    int n2o = D_MODEL * D_MODEL / 2;
    int n2tot = n2x + n2q + n2o;
    round_all<<<(n2tot + 255) / 256, 256>>>(
        (const float2*)x, (__half2*)xh, n2x,
        (const float2*)qkv_w, (__half2*)wq, n2q,
        (const float2*)out_w, (__half2*)wo, n2o);

    // 1) QKV projection -> fp16 (Q columns pre-scaled by 0.125*log2e)
    gemm_mma<<<dim3(N_QKV / 128, M_TOT / 128), 128, GEMM_SMEM>>>(
        xh, wq, qkv_b, nullptr, qkv, N_QKV, D_MODEL, 2);

    // 2) Split-KV-column causal flash attention -> fp16
    flash_attn_mma<<<dim3(SEQ / 64, N_HEADS, BATCH), 128, ATT_SMEM>>>(qkv, att);

    // 3) Output projection -> fp32 final
    gemm_mma<<<dim3(D_MODEL / 128, M_TOT / 128), 128, GEMM_SMEM>>>(
        att, wo, out_b, out, nullptr, D_MODEL, D_MODEL, 0);
}